// round 5
// baseline (speedup 1.0000x reference)
#include <cuda_runtime.h>

#define BATCH 4
#define DS 16
#define NO 2048
#define NR 16384
#define DR 8
#define DE 64
#define DX 8
#define DP 64
#define NC 10

#define RSPLIT 8
#define NRS (NR / RSPLIT)   // 2048 r per split

typedef unsigned long long u64;

// Scratch (allocation-free rule: __device__ globals)
__device__ float g_E[(size_t)BATCH * DE * NR];                     // 16.8 MB
__device__ float g_Ehp[(size_t)RSPLIT * BATCH * DE * NO];          // 16.8 MB partials

// ---- packed fp32x2 helpers (Blackwell FFMA2; PTX-only path) ----
__device__ __forceinline__ u64 ffma2(u64 a, u64 b, u64 c) {
    u64 d;
    asm("fma.rn.f32x2 %0, %1, %2, %3;" : "=l"(d) : "l"(a), "l"(b), "l"(c));
    return d;
}
__device__ __forceinline__ u64 pack2(float lo, float hi) {
    u64 r;
    asm("mov.b64 %0, {%1, %2};" : "=l"(r) : "f"(lo), "f"(hi));
    return r;
}
__device__ __forceinline__ float2 unpack2(u64 v) {
    float2 f;
    asm("mov.b64 {%0, %1}, %2;" : "=f"(f.x), "=f"(f.y) : "l"(v));
    return f;
}

// ============================================================================
// Kernel A: E = W_r @ [O@R_s ; O@R_r ; R_a] + b_r        (B, DE, NR)
// grid (NR/512, BATCH), block 512. One thread owns one relation column r.
// O staged in smem as d-pairs; read 4x LDS.128 (broadcast) per o.
// ============================================================================
__global__ void __launch_bounds__(512, 1)
kernelA(const float* __restrict__ O, const float* __restrict__ Rs,
        const float* __restrict__ Rr, const float* __restrict__ Ra,
        const float* __restrict__ Wr, const float* __restrict__ br)
{
    extern __shared__ u64 sm[];
    u64* sO = sm;                       // [NO][8] d-pairs (= [NO][4] ulonglong2)
    u64* sW = sm + (size_t)NO * 8;      // [DE][20] f-pairs
    float* sbr = (float*)(sW + DE * 20);

    const int tid = threadIdx.x;
    const int b   = blockIdx.y;
    const int r   = blockIdx.x * 512 + tid;

    // stage O (16 x 2048) as pairs over d
    const float* Ob = O + (size_t)b * DS * NO;
    for (int idx = tid; idx < 8 * NO; idx += 512) {
        int d2 = idx / NO, o = idx - d2 * NO;
        sO[(size_t)o * 8 + d2] = pack2(Ob[(size_t)(2 * d2) * NO + o],
                                       Ob[(size_t)(2 * d2 + 1) * NO + o]);
    }
    // stage W_r (64 x 40) as pairs over f
    for (int idx = tid; idx < DE * 20; idx += 512) {
        int e = idx / 20, f2 = idx - e * 20;
        float2 w = *(const float2*)(Wr + (size_t)e * 40 + 2 * f2);
        sW[(size_t)e * 20 + f2] = pack2(w.x, w.y);
    }
    if (tid < DE) sbr[tid] = br[tid];
    __syncthreads();

    const float* ps = Rs + (size_t)b * NO * NR + r;
    const float* pr = Rr + (size_t)b * NO * NR + r;

    u64 m1[8], m2[8];
#pragma unroll
    for (int i = 0; i < 8; i++) { m1[i] = 0ull; m2[i] = 0ull; }

    const int U = 8;
    float as[2][U], ar[2][U];
#pragma unroll
    for (int u = 0; u < U; u++) {
        as[0][u] = ps[(size_t)u * NR];
        ar[0][u] = pr[(size_t)u * NR];
    }
    int buf = 0;
    for (int o = 0; o < NO; o += U) {
        int nb = buf ^ 1;
        if (o + U < NO) {
#pragma unroll
            for (int u = 0; u < U; u++) {
                as[nb][u] = ps[(size_t)(o + U + u) * NR];
                ar[nb][u] = pr[(size_t)(o + U + u) * NR];
            }
        }
#pragma unroll
        for (int u = 0; u < U; u++) {
            u64 bs  = pack2(as[buf][u], as[buf][u]);
            u64 brr = pack2(ar[buf][u], ar[buf][u]);
            const ulonglong2* orow = (const ulonglong2*)(sO + (size_t)(o + u) * 8);
            ulonglong2 q0 = orow[0];
            ulonglong2 q1 = orow[1];
            ulonglong2 q2 = orow[2];
            ulonglong2 q3 = orow[3];
            m1[0] = ffma2(q0.x, bs,  m1[0]);  m2[0] = ffma2(q0.x, brr, m2[0]);
            m1[1] = ffma2(q0.y, bs,  m1[1]);  m2[1] = ffma2(q0.y, brr, m2[1]);
            m1[2] = ffma2(q1.x, bs,  m1[2]);  m2[2] = ffma2(q1.x, brr, m2[2]);
            m1[3] = ffma2(q1.y, bs,  m1[3]);  m2[3] = ffma2(q1.y, brr, m2[3]);
            m1[4] = ffma2(q2.x, bs,  m1[4]);  m2[4] = ffma2(q2.x, brr, m2[4]);
            m1[5] = ffma2(q2.y, bs,  m1[5]);  m2[5] = ffma2(q2.y, brr, m2[5]);
            m1[6] = ffma2(q3.x, bs,  m1[6]);  m2[6] = ffma2(q3.x, brr, m2[6]);
            m1[7] = ffma2(q3.y, bs,  m1[7]);  m2[7] = ffma2(q3.y, brr, m2[7]);
        }
        buf = nb;
    }

    // R_a pairs
    const float* Rab = Ra + (size_t)b * DR * NR + r;
    u64 rap[4];
#pragma unroll
    for (int j = 0; j < 4; j++)
        rap[j] = pack2(Rab[(size_t)(2 * j) * NR], Rab[(size_t)(2 * j + 1) * NR]);

    // E = W_r @ B + b_r  (dot over 40 features as 20 packed pairs)
    float* Eb = g_E + (size_t)b * DE * NR + r;
#pragma unroll 4
    for (int e = 0; e < DE; e++) {
        const u64* wrow = sW + (size_t)e * 20;
        u64 acc = 0ull;
#pragma unroll
        for (int f2 = 0; f2 < 8; f2++)  acc = ffma2(wrow[f2],      m1[f2],  acc);
#pragma unroll
        for (int f2 = 0; f2 < 8; f2++)  acc = ffma2(wrow[8 + f2],  m2[f2],  acc);
#pragma unroll
        for (int j = 0; j < 4; j++)     acc = ffma2(wrow[16 + j],  rap[j],  acc);
        float2 a = unpack2(acc);
        Eb[(size_t)e * NR] = a.x + a.y + sbr[e];
    }
}

// ============================================================================
// Kernel B: E_hat[e,o] += sum_{r in split} E[e,r] * R_r[o,r]
// grid (NO/128, BATCH, RSPLIT) = 512 CTAs, block 128 (4 warps), 4 CTAs/SM.
// CTA tile 64e x 128o over 2048 r. Thread tile 8e x 8o (32 FFMA2 / rr).
// sR2 holds DUPLICATED (v,v) pairs -> FFMA2 broadcast operand is one LDS.64,
// no register-duplication MOVs in the inner loop.
// ============================================================================
#define KCB 32
#define PEB 68    // sE pitch (floats): 16B-aligned rows, conflict-free
#define PRB 258   // sR2 pitch (floats)

__global__ void __launch_bounds__(128, 4)
kernelB(const float* __restrict__ Rr)
{
    __shared__ __align__(16) float sE[KCB * PEB];    // [rr][e]        8.7 KB
    __shared__ __align__(16) float sR2[KCB * PRB];   // [rr][2*o] dup 33.0 KB

    const int tid = threadIdx.x;
    const int tx  = tid & 15;     // o group: o = o0 + tx + 16j
    const int ty  = tid >> 4;     // 0..7 : e = 8*ty + 0..7
    const int o0  = blockIdx.x * 128;
    const int b   = blockIdx.y;
    const int rb0 = blockIdx.z * NRS;

    const float* Eg = g_E + (size_t)b * DE * NR;
    const float* Rg = Rr  + (size_t)b * NO * NR;

    u64 acc[4][8];
#pragma unroll
    for (int i = 0; i < 4; i++)
#pragma unroll
        for (int j = 0; j < 8; j++) acc[i][j] = 0ull;

    // staging maps
    const int eS = tid & 63;      // E row this thread stages
    const int hS = tid >> 6;      // rr half (0/1), 16 rr each

    for (int kc = 0; kc < NRS / KCB; kc++) {
        const int rbase = rb0 + kc * KCB;

        // ---- global loads into regs (issued before the barrier) ----
        float4 ev[4];
        {
            const float4* ep = (const float4*)(Eg + (size_t)eS * NR + rbase + hS * 16);
#pragma unroll
            for (int q = 0; q < 4; q++) ev[q] = ep[q];
        }
        float4 rv[8];
        {
            const float4* rp = (const float4*)(Rg + (size_t)(o0 + tid) * NR + rbase);
#pragma unroll
            for (int q = 0; q < 8; q++) rv[q] = rp[q];
        }

        __syncthreads();   // previous chunk's compute done before overwrite

        // ---- stores: sE transposed [rr][e]; sR2 duplicated pairs [rr][2o] ----
#pragma unroll
        for (int q = 0; q < 4; q++) {
            int k = hS * 16 + 4 * q;
            sE[(k + 0) * PEB + eS] = ev[q].x;
            sE[(k + 1) * PEB + eS] = ev[q].y;
            sE[(k + 2) * PEB + eS] = ev[q].z;
            sE[(k + 3) * PEB + eS] = ev[q].w;
        }
#pragma unroll
        for (int q = 0; q < 8; q++) {
            int k = 4 * q;
            *(float2*)&sR2[(k + 0) * PRB + 2 * tid] = make_float2(rv[q].x, rv[q].x);
            *(float2*)&sR2[(k + 1) * PRB + 2 * tid] = make_float2(rv[q].y, rv[q].y);
            *(float2*)&sR2[(k + 2) * PRB + 2 * tid] = make_float2(rv[q].z, rv[q].z);
            *(float2*)&sR2[(k + 3) * PRB + 2 * tid] = make_float2(rv[q].w, rv[q].w);
        }
        __syncthreads();

        // ---- compute: per rr: 2 LDS.128 (E pairs) + 8 LDS.64 (R dup) + 32 FFMA2
#pragma unroll 4
        for (int rr = 0; rr < KCB; rr++) {
            ulonglong2 e01 = *(const ulonglong2*)&sE[rr * PEB + 8 * ty];
            ulonglong2 e23 = *(const ulonglong2*)&sE[rr * PEB + 8 * ty + 4];
#pragma unroll
            for (int j = 0; j < 8; j++) {
                u64 rj = *(const u64*)&sR2[rr * PRB + 2 * tx + 32 * j];
                acc[0][j] = ffma2(e01.x, rj, acc[0][j]);
                acc[1][j] = ffma2(e01.y, rj, acc[1][j]);
                acc[2][j] = ffma2(e23.x, rj, acc[2][j]);
                acc[3][j] = ffma2(e23.y, rj, acc[3][j]);
            }
        }
    }

    // ---- write partial tile ----
    float* out = g_Ehp + (((size_t)blockIdx.z * BATCH + b) * DE) * NO;
#pragma unroll
    for (int ep = 0; ep < 4; ep++) {
        int e = 8 * ty + 2 * ep;
#pragma unroll
        for (int j = 0; j < 8; j++) {
            float2 v = unpack2(acc[ep][j]);
            int o = o0 + tx + 16 * j;
            out[(size_t)e * NO + o]       = v.x;
            out[(size_t)(e + 1) * NO + o] = v.y;
        }
    }
}

// ============================================================================
// Kernel C: P = W_o@[O;X;sum_s E_hat_s]+b_o ; scores = W_s@P+b_s ; softmax
// grid (NO/256, BATCH), block 256. Thread per object column.
// ============================================================================
__global__ void __launch_bounds__(256, 1)
kernelC(const float* __restrict__ O, const float* __restrict__ X,
        const float* __restrict__ Wo, const float* __restrict__ bo,
        const float* __restrict__ Ws, const float* __restrict__ bs,
        float* __restrict__ out)
{
    __shared__ u64 sWo[88 * 32];   // [f][p-pair]
    __shared__ u64 sWs[NC * 32];   // [c][p-pair]
    __shared__ float sbo[DP];
    __shared__ float sbs[NC];

    const int tid = threadIdx.x;
    const int b   = blockIdx.y;
    const int o   = blockIdx.x * 256 + tid;

    for (int idx = tid; idx < 88 * 32; idx += 256) {
        int f = idx >> 5, p2 = idx & 31;
        sWo[f * 32 + p2] = pack2(Wo[(size_t)(2 * p2) * 88 + f],
                                 Wo[(size_t)(2 * p2 + 1) * 88 + f]);
    }
    for (int idx = tid; idx < NC * 32; idx += 256) {
        int c = idx >> 5, p2 = idx & 31;
        float2 w = *(const float2*)(Ws + (size_t)c * DP + 2 * p2);
        sWs[c * 32 + p2] = pack2(w.x, w.y);
    }
    if (tid < DP) sbo[tid] = bo[tid];
    if (tid < NC) sbs[tid] = bs[tid];
    __syncthreads();

    u64 P[32];
#pragma unroll
    for (int p2 = 0; p2 < 32; p2++) P[p2] = pack2(sbo[2 * p2], sbo[2 * p2 + 1]);

    const float* Ob  = O + (size_t)b * DS * NO + o;
    const float* Xb  = X + (size_t)b * DX * NO + o;
    const float* Ehb = g_Ehp + ((size_t)b * DE) * NO + o;
    const size_t SSTR = (size_t)BATCH * DE * NO;

#pragma unroll 4
    for (int f = 0; f < DS; f++) {
        float cf = Ob[(size_t)f * NO];
        u64 c2 = pack2(cf, cf);
        const u64* wrow = sWo + f * 32;
#pragma unroll
        for (int p2 = 0; p2 < 32; p2++) P[p2] = ffma2(wrow[p2], c2, P[p2]);
    }
#pragma unroll 4
    for (int f = 0; f < DX; f++) {
        float cf = Xb[(size_t)f * NO];
        u64 c2 = pack2(cf, cf);
        const u64* wrow = sWo + (DS + f) * 32;
#pragma unroll
        for (int p2 = 0; p2 < 32; p2++) P[p2] = ffma2(wrow[p2], c2, P[p2]);
    }
#pragma unroll 2
    for (int f = 0; f < DE; f++) {
        const float* ep = Ehb + (size_t)f * NO;
        float cf = 0.f;
#pragma unroll
        for (int s = 0; s < RSPLIT; s++) cf += ep[s * SSTR];
        u64 c2 = pack2(cf, cf);
        const u64* wrow = sWo + (DS + DX + f) * 32;
#pragma unroll
        for (int p2 = 0; p2 < 32; p2++) P[p2] = ffma2(wrow[p2], c2, P[p2]);
    }

    float sc[NC];
#pragma unroll
    for (int c = 0; c < NC; c++) {
        const u64* wrow = sWs + c * 32;
        u64 acc = 0ull;
#pragma unroll
        for (int p2 = 0; p2 < 32; p2++) acc = ffma2(wrow[p2], P[p2], acc);
        float2 a = unpack2(acc);
        sc[c] = a.x + a.y + sbs[c];
    }

    float mx = sc[0];
#pragma unroll
    for (int c = 1; c < NC; c++) mx = fmaxf(mx, sc[c]);
    float sum = 0.f;
#pragma unroll
    for (int c = 0; c < NC; c++) { sc[c] = expf(sc[c] - mx); sum += sc[c]; }
    float inv = 1.f / sum;
#pragma unroll
    for (int c = 0; c < NC; c++)
        out[((size_t)b * NC + c) * NO + o] = sc[c] * inv;
}

// ============================================================================
extern "C" void kernel_launch(void* const* d_in, const int* in_sizes, int n_in,
                              void* d_out, int out_size)
{
    const float* O  = (const float*)d_in[0];
    const float* Rs = (const float*)d_in[1];
    const float* Rr = (const float*)d_in[2];
    const float* Ra = (const float*)d_in[3];
    const float* X  = (const float*)d_in[4];
    const float* Wr = (const float*)d_in[5];
    const float* br = (const float*)d_in[6];
    const float* Wo = (const float*)d_in[7];
    const float* bo = (const float*)d_in[8];
    const float* Ws = (const float*)d_in[9];
    const float* bs = (const float*)d_in[10];
    float* out = (float*)d_out;
    (void)in_sizes; (void)n_in; (void)out_size;

    int smA = NO * 8 * 8 + DE * 20 * 8 + DE * 4;  // 141568 B
    cudaFuncSetAttribute(kernelA, cudaFuncAttributeMaxDynamicSharedMemorySize, smA);

    kernelA<<<dim3(NR / 512, BATCH), 512, smA>>>(O, Rs, Rr, Ra, Wr, br);
    kernelB<<<dim3(NO / 128, BATCH, RSPLIT), 128>>>(Rr);
    kernelC<<<dim3(NO / 256, BATCH), 256>>>(O, X, Wo, bo, Ws, bs, out);
}

// round 7
// speedup vs baseline: 1.6601x; 1.6601x over previous
#include <cuda_runtime.h>
#include <cstdint>

#define BATCH 4
#define DS 16
#define NO 2048
#define NR 16384
#define DR 8
#define DE 64
#define DX 8
#define DP 64
#define NC 10

// kernelB tiling
#define ZB 2
#define KZ (NR / ZB)        // 8192 r per z-split
#define KC 32               // r per chunk
#define NCH (KZ / KC)       // 256 chunks
#define PITCH 80            // smem row pitch in bytes (40 bf16): 16B-aligned, conflict-free

typedef unsigned long long u64;

// Scratch (allocation-free rule: __device__ globals)
__device__ float g_E[(size_t)BATCH * DE * NR];                 // 16.8 MB  [b][e][r]
__device__ float g_Ehp[(size_t)ZB * BATCH * NO * DE];          // 4 MB     [z][b][o][e]

// ---- packed fp32x2 helpers (FFMA2) ----
__device__ __forceinline__ u64 ffma2(u64 a, u64 b, u64 c) {
    u64 d;
    asm("fma.rn.f32x2 %0, %1, %2, %3;" : "=l"(d) : "l"(a), "l"(b), "l"(c));
    return d;
}
__device__ __forceinline__ u64 pack2(float lo, float hi) {
    u64 r;
    asm("mov.b64 %0, {%1, %2};" : "=l"(r) : "f"(lo), "f"(hi));
    return r;
}
__device__ __forceinline__ float2 unpack2(u64 v) {
    float2 f;
    asm("mov.b64 {%0, %1}, %2;" : "=f"(f.x), "=f"(f.y) : "l"(v));
    return f;
}
__device__ __forceinline__ uint32_t smem_u32(const void* p) {
    uint32_t a;
    asm("{ .reg .u64 t; cvta.to.shared.u64 t, %1; cvt.u32.u64 %0, t; }" : "=r"(a) : "l"(p));
    return a;
}
// split (x0,x1) -> packed bf16x2 hi limb + packed bf16x2 lo residual
__device__ __forceinline__ void split2(float x0, float x1, uint32_t& hi, uint32_t& lo) {
    asm("cvt.rn.bf16x2.f32 %0, %1, %2;" : "=r"(hi) : "f"(x1), "f"(x0));
    float h0 = __uint_as_float(hi << 16);
    float h1 = __uint_as_float(hi & 0xFFFF0000u);
    float r0 = x0 - h0, r1 = x1 - h1;
    asm("cvt.rn.bf16x2.f32 %0, %1, %2;" : "=r"(lo) : "f"(r1), "f"(r0));
}
__device__ __forceinline__ void sts64(uint32_t a, uint32_t x, uint32_t y) {
    asm volatile("st.shared.v2.b32 [%0], {%1,%2};" :: "r"(a), "r"(x), "r"(y) : "memory");
}
__device__ __forceinline__ void ldm_x4(uint32_t* r, uint32_t addr) {
    asm volatile("ldmatrix.sync.aligned.m8n8.x4.shared.b16 {%0,%1,%2,%3}, [%4];"
                 : "=r"(r[0]), "=r"(r[1]), "=r"(r[2]), "=r"(r[3]) : "r"(addr));
}
__device__ __forceinline__ void mma16816(float* d, const uint32_t* a, const uint32_t* b) {
    asm volatile(
        "mma.sync.aligned.m16n8k16.row.col.f32.bf16.bf16.f32 "
        "{%0,%1,%2,%3}, {%4,%5,%6,%7}, {%8,%9}, {%0,%1,%2,%3};"
        : "+f"(d[0]), "+f"(d[1]), "+f"(d[2]), "+f"(d[3])
        : "r"(a[0]), "r"(a[1]), "r"(a[2]), "r"(a[3]), "r"(b[0]), "r"(b[1]));
}

// ============================================================================
// Kernel A: E = W_r @ [O@R_s ; O@R_r ; R_a] + b_r     (B, DE, NR)
// grid (NR/512, BATCH), block 256. Each thread owns 2 relation columns
// (r0, r0+1): each broadcast LDS of O now feeds 2x the FFMA2 work, shifting
// the bottleneck from L1 (65.6%) to the fma pipe. R loads are float2.
// ============================================================================
__global__ void __launch_bounds__(256)
kernelA(const float* __restrict__ O, const float* __restrict__ Rs,
        const float* __restrict__ Rr, const float* __restrict__ Ra,
        const float* __restrict__ Wr, const float* __restrict__ br)
{
    extern __shared__ u64 sm[];
    u64* sO = sm;                       // [NO][8] d-pairs
    u64* sW = sm + (size_t)NO * 8;      // [DE][20] f-pairs
    float* sbr = (float*)(sW + DE * 20);

    const int tid = threadIdx.x;
    const int b   = blockIdx.y;
    const int r0  = blockIdx.x * 512 + 2 * tid;

    const float* Ob = O + (size_t)b * DS * NO;
    for (int idx = tid; idx < 8 * NO; idx += 256) {
        int d2 = idx / NO, o = idx - d2 * NO;
        sO[(size_t)o * 8 + d2] = pack2(Ob[(size_t)(2 * d2) * NO + o],
                                       Ob[(size_t)(2 * d2 + 1) * NO + o]);
    }
    for (int idx = tid; idx < DE * 20; idx += 256) {
        int e = idx / 20, f2 = idx - e * 20;
        float2 w = *(const float2*)(Wr + (size_t)e * 40 + 2 * f2);
        sW[(size_t)e * 20 + f2] = pack2(w.x, w.y);
    }
    if (tid < DE) sbr[tid] = br[tid];
    __syncthreads();

    const float* ps = Rs + (size_t)b * NO * NR + r0;
    const float* pr = Rr + (size_t)b * NO * NR + r0;

    u64 m1[8][2], m2[8][2];
#pragma unroll
    for (int i = 0; i < 8; i++) {
        m1[i][0] = m1[i][1] = 0ull;
        m2[i][0] = m2[i][1] = 0ull;
    }

    const int U = 4;
    float2 as[2][U], ar[2][U];
#pragma unroll
    for (int u = 0; u < U; u++) {
        as[0][u] = *(const float2*)(ps + (size_t)u * NR);
        ar[0][u] = *(const float2*)(pr + (size_t)u * NR);
    }
    int buf = 0;
    for (int o0 = 0; o0 < NO; o0 += U) {
        int nb = buf ^ 1;
        if (o0 + U < NO) {
#pragma unroll
            for (int u = 0; u < U; u++) {
                as[nb][u] = *(const float2*)(ps + (size_t)(o0 + U + u) * NR);
                ar[nb][u] = *(const float2*)(pr + (size_t)(o0 + U + u) * NR);
            }
        }
#pragma unroll
        for (int u = 0; u < U; u++) {
            float2 s = as[buf][u];
            float2 t = ar[buf][u];
            u64 s0 = pack2(s.x, s.x), s1 = pack2(s.y, s.y);
            u64 t0 = pack2(t.x, t.x), t1 = pack2(t.y, t.y);
            const ulonglong2* orow = (const ulonglong2*)(sO + (size_t)(o0 + u) * 8);
            ulonglong2 q0 = orow[0], q1 = orow[1], q2 = orow[2], q3 = orow[3];
            m1[0][0] = ffma2(q0.x, s0, m1[0][0]);  m1[0][1] = ffma2(q0.x, s1, m1[0][1]);
            m2[0][0] = ffma2(q0.x, t0, m2[0][0]);  m2[0][1] = ffma2(q0.x, t1, m2[0][1]);
            m1[1][0] = ffma2(q0.y, s0, m1[1][0]);  m1[1][1] = ffma2(q0.y, s1, m1[1][1]);
            m2[1][0] = ffma2(q0.y, t0, m2[1][0]);  m2[1][1] = ffma2(q0.y, t1, m2[1][1]);
            m1[2][0] = ffma2(q1.x, s0, m1[2][0]);  m1[2][1] = ffma2(q1.x, s1, m1[2][1]);
            m2[2][0] = ffma2(q1.x, t0, m2[2][0]);  m2[2][1] = ffma2(q1.x, t1, m2[2][1]);
            m1[3][0] = ffma2(q1.y, s0, m1[3][0]);  m1[3][1] = ffma2(q1.y, s1, m1[3][1]);
            m2[3][0] = ffma2(q1.y, t0, m2[3][0]);  m2[3][1] = ffma2(q1.y, t1, m2[3][1]);
            m1[4][0] = ffma2(q2.x, s0, m1[4][0]);  m1[4][1] = ffma2(q2.x, s1, m1[4][1]);
            m2[4][0] = ffma2(q2.x, t0, m2[4][0]);  m2[4][1] = ffma2(q2.x, t1, m2[4][1]);
            m1[5][0] = ffma2(q2.y, s0, m1[5][0]);  m1[5][1] = ffma2(q2.y, s1, m1[5][1]);
            m2[5][0] = ffma2(q2.y, t0, m2[5][0]);  m2[5][1] = ffma2(q2.y, t1, m2[5][1]);
            m1[6][0] = ffma2(q3.x, s0, m1[6][0]);  m1[6][1] = ffma2(q3.x, s1, m1[6][1]);
            m2[6][0] = ffma2(q3.x, t0, m2[6][0]);  m2[6][1] = ffma2(q3.x, t1, m2[6][1]);
            m1[7][0] = ffma2(q3.y, s0, m1[7][0]);  m1[7][1] = ffma2(q3.y, s1, m1[7][1]);
            m2[7][0] = ffma2(q3.y, t0, m2[7][0]);  m2[7][1] = ffma2(q3.y, t1, m2[7][1]);
        }
        buf = nb;
    }

    const float* Rab = Ra + (size_t)b * DR * NR + r0;
    u64 rap[2][4];
#pragma unroll
    for (int c = 0; c < 2; c++)
#pragma unroll
        for (int j = 0; j < 4; j++)
            rap[c][j] = pack2(Rab[(size_t)(2 * j) * NR + c], Rab[(size_t)(2 * j + 1) * NR + c]);

    float* Eb = g_E + (size_t)b * DE * NR + r0;
#pragma unroll 2
    for (int e = 0; e < DE; e++) {
        const u64* wrow = sW + (size_t)e * 20;
        u64 a0 = 0ull, a1 = 0ull;
#pragma unroll
        for (int f2 = 0; f2 < 8; f2++) {
            a0 = ffma2(wrow[f2], m1[f2][0], a0);
            a1 = ffma2(wrow[f2], m1[f2][1], a1);
        }
#pragma unroll
        for (int f2 = 0; f2 < 8; f2++) {
            a0 = ffma2(wrow[8 + f2], m2[f2][0], a0);
            a1 = ffma2(wrow[8 + f2], m2[f2][1], a1);
        }
#pragma unroll
        for (int j = 0; j < 4; j++) {
            a0 = ffma2(wrow[16 + j], rap[0][j], a0);
            a1 = ffma2(wrow[16 + j], rap[1][j], a1);
        }
        float2 v0 = unpack2(a0), v1 = unpack2(a1);
        *(float2*)(Eb + (size_t)e * NR) = make_float2(v0.x + v0.y + sbr[e],
                                                      v1.x + v1.y + sbr[e]);
    }
}

// ============================================================================
// Kernel B: E_hat[z][b][o][e] = sum_{r in z} R_r[b,o,r] * E[b,e,r]
// mma.sync.m16n8k16 bf16 (baseline PTX -> tensor pipe), 2-limb split,
// 3 products (hihi + hilo + lohi), fp32 acc in registers.
// CTA 128o x 64e, 8 warps (4x2), warp tile 32o x 32e, KC=32, reg-prefetch.
// grid (16, BATCH, ZB) = 128 CTAs, block 256.
// ============================================================================
__global__ void __launch_bounds__(256)
kernelB(const float* __restrict__ Rr)
{
    // A tile: 128 rows (o) x 32 k bf16, pitch 80B. B tile: 64 rows (e) x 32 k.
    __shared__ __align__(128) char sAh[128 * PITCH];
    __shared__ __align__(128) char sAl[128 * PITCH];
    __shared__ __align__(128) char sBh[64 * PITCH];
    __shared__ __align__(128) char sBl[64 * PITCH];

    const int tid = threadIdx.x;
    const int wid = tid >> 5;
    const int lid = tid & 31;
    const int wm  = wid & 3;        // warp M group: o rows wm*32..+31
    const int wn  = wid >> 2;       // warp N group: e cols wn*32..+31
    const int o0  = blockIdx.x * 128;
    const int b   = blockIdx.y;
    const int z   = blockIdx.z;

    const uint32_t uAh = smem_u32(sAh), uAl = smem_u32(sAl);
    const uint32_t uBh = smem_u32(sBh), uBl = smem_u32(sBl);

    const float* Ag = Rr  + (size_t)b * NO * NR + (size_t)z * KZ;   // rows: o
    const float* Bg = g_E + (size_t)b * DE * NR + (size_t)z * KZ;   // rows: e

    // staging: A thread -> row t>>1, k-half (t&1)*16 (4 float4)
    //          B thread -> row t>>2, k-q (t&3)*8 (2 float4)
    const int arow = tid >> 1, akh = (tid & 1) * 16;
    const int brow = tid >> 2, bkq = (tid & 3) * 8;

    // ldmatrix lane addressing (non-trans; K-major rows make B naturally col-major)
    // A frag (m16k16): mi = lid>>3: row = base + (mi&1)*8 + (lid&7), k = ks*16 + (mi>>1)*8
    const uint32_t a_lrow = (uint32_t)((wm * 32) + (((lid >> 3) & 1) * 8) + (lid & 7));
    const uint32_t a_lcol = (uint32_t)((lid >> 4) * 8);
    // B frag pair (two n-tiles): mi = lid>>3: e = base + (mi>>1)*8 + (lid&7), k = ks*16 + (mi&1)*8
    const uint32_t b_lrow = (uint32_t)((wn * 32) + (((lid >> 3) >> 1) * 8) + (lid & 7));
    const uint32_t b_lcol = (uint32_t)(((lid >> 3) & 1) * 8);

    float acc[2][4][4];
#pragma unroll
    for (int i = 0; i < 2; i++)
#pragma unroll
        for (int j = 0; j < 4; j++)
#pragma unroll
            for (int v = 0; v < 4; v++) acc[i][j][v] = 0.f;

    float4 av[4], bv[2];
    // prologue: chunk 0 -> regs
    {
        const float* ap = Ag + (size_t)(o0 + arow) * NR + akh;
#pragma unroll
        for (int q = 0; q < 4; q++) av[q] = *(const float4*)(ap + 4 * q);
        const float* bp = Bg + (size_t)brow * NR + bkq;
#pragma unroll
        for (int q = 0; q < 2; q++) bv[q] = *(const float4*)(bp + 4 * q);
    }

    for (int kc = 0; kc < NCH; kc++) {
        if (kc > 0) __syncthreads();   // previous compute done before overwrite

        // convert + store regs -> smem
#pragma unroll
        for (int q = 0; q < 4; q++) {
            uint32_t h0, h1, l0, l1;
            split2(av[q].x, av[q].y, h0, l0);
            split2(av[q].z, av[q].w, h1, l1);
            uint32_t off = (uint32_t)arow * PITCH + (uint32_t)(akh + 4 * q) * 2;
            sts64(uAh + off, h0, h1);
            sts64(uAl + off, l0, l1);
        }
#pragma unroll
        for (int q = 0; q < 2; q++) {
            uint32_t h0, h1, l0, l1;
            split2(bv[q].x, bv[q].y, h0, l0);
            split2(bv[q].z, bv[q].w, h1, l1);
            uint32_t off = (uint32_t)brow * PITCH + (uint32_t)(bkq + 4 * q) * 2;
            sts64(uBh + off, h0, h1);
            sts64(uBl + off, l0, l1);
        }
        __syncthreads();

        // prefetch next chunk (overlaps with compute below)
        if (kc + 1 < NCH) {
            const int rb = (kc + 1) * KC;
            const float* ap = Ag + (size_t)(o0 + arow) * NR + rb + akh;
#pragma unroll
            for (int q = 0; q < 4; q++) av[q] = *(const float4*)(ap + 4 * q);
            const float* bp = Bg + (size_t)brow * NR + rb + bkq;
#pragma unroll
            for (int q = 0; q < 2; q++) bv[q] = *(const float4*)(bp + 4 * q);
        }

        // compute: per k-step: 4+4 ldmatrix.x4, 24 mma
#pragma unroll
        for (int ks = 0; ks < 2; ks++) {
            const uint32_t koff = (uint32_t)(ks * 16) * 2;
            uint32_t ah[2][4], al[2][4];   // [mt][reg]
            uint32_t bh[4][2], bl[4][2];   // [nt][reg]
#pragma unroll
            for (int mt = 0; mt < 2; mt++) {
                uint32_t addr = (a_lrow + mt * 16) * PITCH + a_lcol * 2 + koff;
                ldm_x4(ah[mt], uAh + addr);
                ldm_x4(al[mt], uAl + addr);
            }
#pragma unroll
            for (int tp = 0; tp < 2; tp++) {
                uint32_t addr = (b_lrow + tp * 16) * PITCH + b_lcol * 2 + koff;
                uint32_t rh[4], rl[4];
                ldm_x4(rh, uBh + addr);
                ldm_x4(rl, uBl + addr);
                bh[2 * tp][0] = rh[0]; bh[2 * tp][1] = rh[1];
                bh[2 * tp + 1][0] = rh[2]; bh[2 * tp + 1][1] = rh[3];
                bl[2 * tp][0] = rl[0]; bl[2 * tp][1] = rl[1];
                bl[2 * tp + 1][0] = rl[2]; bl[2 * tp + 1][1] = rl[3];
            }
#pragma unroll
            for (int mt = 0; mt < 2; mt++)
#pragma unroll
                for (int nt = 0; nt < 4; nt++) {
                    mma16816(acc[mt][nt], ah[mt], bh[nt]);   // hi*hi
                    mma16816(acc[mt][nt], ah[mt], bl[nt]);   // hi*lo
                    mma16816(acc[mt][nt], al[mt], bh[nt]);   // lo*hi
                }
        }
    }

    // epilogue: D frag -> g_Ehp[z][b][o][e]
    float* outb = g_Ehp + ((size_t)(z * BATCH + b) * NO) * DE;
#pragma unroll
    for (int mt = 0; mt < 2; mt++) {
        int o = o0 + wm * 32 + mt * 16 + (lid >> 2);
#pragma unroll
        for (int nt = 0; nt < 4; nt++) {
            int e = wn * 32 + nt * 8 + (lid & 3) * 2;
            float* p = outb + (size_t)o * DE + e;
            *(float2*)p = make_float2(acc[mt][nt][0], acc[mt][nt][1]);
            *(float2*)(p + 8 * DE) = make_float2(acc[mt][nt][2], acc[mt][nt][3]);
        }
    }
}

// ============================================================================
// Kernel C: P = W_o@[O;X;sum_z E_hat_z]+b_o ; scores = W_s@P+b_s ; softmax
// ============================================================================
__global__ void __launch_bounds__(256, 1)
kernelC(const float* __restrict__ O, const float* __restrict__ X,
        const float* __restrict__ Wo, const float* __restrict__ bo,
        const float* __restrict__ Ws, const float* __restrict__ bs,
        float* __restrict__ out)
{
    __shared__ u64 sWo[88 * 32];
    __shared__ u64 sWs[NC * 32];
    __shared__ float sbo[DP];
    __shared__ float sbs[NC];

    const int tid = threadIdx.x;
    const int b   = blockIdx.y;
    const int o   = blockIdx.x * 256 + tid;

    for (int idx = tid; idx < 88 * 32; idx += 256) {
        int f = idx >> 5, p2 = idx & 31;
        sWo[f * 32 + p2] = pack2(Wo[(size_t)(2 * p2) * 88 + f],
                                 Wo[(size_t)(2 * p2 + 1) * 88 + f]);
    }
    for (int idx = tid; idx < NC * 32; idx += 256) {
        int c = idx >> 5, p2 = idx & 31;
        float2 w = *(const float2*)(Ws + (size_t)c * DP + 2 * p2);
        sWs[c * 32 + p2] = pack2(w.x, w.y);
    }
    if (tid < DP) sbo[tid] = bo[tid];
    if (tid < NC) sbs[tid] = bs[tid];
    __syncthreads();

    u64 P[32];
#pragma unroll
    for (int p2 = 0; p2 < 32; p2++) P[p2] = pack2(sbo[2 * p2], sbo[2 * p2 + 1]);

    const float* Ob = O + (size_t)b * DS * NO + o;
    const float* Xb = X + (size_t)b * DX * NO + o;

#pragma unroll 4
    for (int f = 0; f < DS; f++) {
        float cf = Ob[(size_t)f * NO];
        u64 c2 = pack2(cf, cf);
        const u64* wrow = sWo + f * 32;
#pragma unroll
        for (int p2 = 0; p2 < 32; p2++) P[p2] = ffma2(wrow[p2], c2, P[p2]);
    }
#pragma unroll 4
    for (int f = 0; f < DX; f++) {
        float cf = Xb[(size_t)f * NO];
        u64 c2 = pack2(cf, cf);
        const u64* wrow = sWo + (DS + f) * 32;
#pragma unroll
        for (int p2 = 0; p2 < 32; p2++) P[p2] = ffma2(wrow[p2], c2, P[p2]);
    }
    // E_hat: [z][b][o][e], contiguous in e
    const float* e0p = g_Ehp + ((size_t)b * NO + o) * DE;
    const float* e1p = e0p + (size_t)BATCH * NO * DE;
#pragma unroll 4
    for (int f4 = 0; f4 < 16; f4++) {
        float4 v0 = *(const float4*)(e0p + 4 * f4);
        float4 v1 = *(const float4*)(e1p + 4 * f4);
        float cf[4] = {v0.x + v1.x, v0.y + v1.y, v0.z + v1.z, v0.w + v1.w};
#pragma unroll
        for (int j = 0; j < 4; j++) {
            u64 c2 = pack2(cf[j], cf[j]);
            const u64* wrow = sWo + (DS + DX + 4 * f4 + j) * 32;
#pragma unroll
            for (int p2 = 0; p2 < 32; p2++) P[p2] = ffma2(wrow[p2], c2, P[p2]);
        }
    }

    float sc[NC];
#pragma unroll
    for (int c = 0; c < NC; c++) {
        const u64* wrow = sWs + c * 32;
        u64 acc = 0ull;
#pragma unroll
        for (int p2 = 0; p2 < 32; p2++) acc = ffma2(wrow[p2], P[p2], acc);
        float2 a = unpack2(acc);
        sc[c] = a.x + a.y + sbs[c];
    }

    float mx = sc[0];
#pragma unroll
    for (int c = 1; c < NC; c++) mx = fmaxf(mx, sc[c]);
    float sum = 0.f;
#pragma unroll
    for (int c = 0; c < NC; c++) { sc[c] = expf(sc[c] - mx); sum += sc[c]; }
    float inv = 1.f / sum;
#pragma unroll
    for (int c = 0; c < NC; c++)
        out[((size_t)b * NC + c) * NO + o] = sc[c] * inv;
}

// ============================================================================
extern "C" void kernel_launch(void* const* d_in, const int* in_sizes, int n_in,
                              void* d_out, int out_size)
{
    const float* O  = (const float*)d_in[0];
    const float* Rs = (const float*)d_in[1];
    const float* Rr = (const float*)d_in[2];
    const float* Ra = (const float*)d_in[3];
    const float* X  = (const float*)d_in[4];
    const float* Wr = (const float*)d_in[5];
    const float* br = (const float*)d_in[6];
    const float* Wo = (const float*)d_in[7];
    const float* bo = (const float*)d_in[8];
    const float* Ws = (const float*)d_in[9];
    const float* bs = (const float*)d_in[10];
    float* out = (float*)d_out;
    (void)in_sizes; (void)n_in; (void)out_size;

    int smA = NO * 8 * 8 + DE * 20 * 8 + DE * 4;   // 141568 B
    cudaFuncSetAttribute(kernelA, cudaFuncAttributeMaxDynamicSharedMemorySize, smA);

    kernelA<<<dim3(NR / 512, BATCH), 256, smA>>>(O, Rs, Rr, Ra, Wr, br);
    kernelB<<<dim3(NO / 128, BATCH, ZB), 256>>>(Rr);
    kernelC<<<dim3(NO / 256, BATCH), 256>>>(O, X, Wo, bo, Ws, bs, out);
}

// round 8
// speedup vs baseline: 1.7319x; 1.0433x over previous
#include <cuda_runtime.h>
#include <cstdint>

#define BATCH 4
#define DS 16
#define NO 2048
#define NR 16384
#define DR 8
#define DE 64
#define DX 8
#define DP 64
#define NC 10

// kernelA o-chunking
#define OCH 512

// kernelB tiling
#define ZB 4
#define KZ (NR / ZB)        // 4096 r per z-split
#define KC 32               // r per chunk
#define NCH (KZ / KC)       // 128 chunks
#define PITCH 80            // smem row pitch in bytes (40 bf16): conflict-free

typedef unsigned long long u64;

// Scratch (allocation-free rule: __device__ globals)
__device__ float g_E[(size_t)BATCH * DE * NR];                 // 16.8 MB  [b][e][r]
__device__ float g_Ehp[(size_t)ZB * BATCH * NO * DE];          // 8.4 MB   [z][b][o][e]

// ---- packed fp32x2 helpers (FFMA2) ----
__device__ __forceinline__ u64 ffma2(u64 a, u64 b, u64 c) {
    u64 d;
    asm("fma.rn.f32x2 %0, %1, %2, %3;" : "=l"(d) : "l"(a), "l"(b), "l"(c));
    return d;
}
__device__ __forceinline__ u64 pack2(float lo, float hi) {
    u64 r;
    asm("mov.b64 %0, {%1, %2};" : "=l"(r) : "f"(lo), "f"(hi));
    return r;
}
__device__ __forceinline__ float2 unpack2(u64 v) {
    float2 f;
    asm("mov.b64 {%0, %1}, %2;" : "=f"(f.x), "=f"(f.y) : "l"(v));
    return f;
}
__device__ __forceinline__ uint32_t smem_u32(const void* p) {
    uint32_t a;
    asm("{ .reg .u64 t; cvta.to.shared.u64 t, %1; cvt.u32.u64 %0, t; }" : "=r"(a) : "l"(p));
    return a;
}
// split (x0,x1) -> packed bf16x2 hi limb + packed bf16x2 lo residual
__device__ __forceinline__ void split2(float x0, float x1, uint32_t& hi, uint32_t& lo) {
    asm("cvt.rn.bf16x2.f32 %0, %1, %2;" : "=r"(hi) : "f"(x1), "f"(x0));
    float h0 = __uint_as_float(hi << 16);
    float h1 = __uint_as_float(hi & 0xFFFF0000u);
    float r0 = x0 - h0, r1 = x1 - h1;
    asm("cvt.rn.bf16x2.f32 %0, %1, %2;" : "=r"(lo) : "f"(r1), "f"(r0));
}
__device__ __forceinline__ void sts64(uint32_t a, uint32_t x, uint32_t y) {
    asm volatile("st.shared.v2.b32 [%0], {%1,%2};" :: "r"(a), "r"(x), "r"(y) : "memory");
}
__device__ __forceinline__ void ldm_x4(uint32_t* r, uint32_t addr) {
    asm volatile("ldmatrix.sync.aligned.m8n8.x4.shared.b16 {%0,%1,%2,%3}, [%4];"
                 : "=r"(r[0]), "=r"(r[1]), "=r"(r[2]), "=r"(r[3]) : "r"(addr));
}
__device__ __forceinline__ void mma16816(float* d, const uint32_t* a, const uint32_t* b) {
    asm volatile(
        "mma.sync.aligned.m16n8k16.row.col.f32.bf16.bf16.f32 "
        "{%0,%1,%2,%3}, {%4,%5,%6,%7}, {%8,%9}, {%0,%1,%2,%3};"
        : "+f"(d[0]), "+f"(d[1]), "+f"(d[2]), "+f"(d[3])
        : "r"(a[0]), "r"(a[1]), "r"(a[2]), "r"(a[3]), "r"(b[0]), "r"(b[1]));
}

// ============================================================================
// Kernel A: E = W_r @ [O@R_s ; O@R_r ; R_a] + b_r     (B, DE, NR)
// grid (NR/512, BATCH), block 256, 2 r-columns per thread.
// O staged in 4 chunks of 512 o-rows (32KB) -> smem 43KB -> 2 CTAs/SM (25% occ)
// for latency hiding. Inner loop unchanged: broadcast LDS.128 + FFMA2.
// ============================================================================
__global__ void __launch_bounds__(256, 2)
kernelA(const float* __restrict__ O, const float* __restrict__ Rs,
        const float* __restrict__ Rr, const float* __restrict__ Ra,
        const float* __restrict__ Wr, const float* __restrict__ br)
{
    extern __shared__ u64 sm[];
    u64* sO = sm;                       // [OCH][8] d-pairs (current chunk)
    u64* sW = sm + (size_t)OCH * 8;     // [DE][20] f-pairs
    float* sbr = (float*)(sW + DE * 20);

    const int tid = threadIdx.x;
    const int b   = blockIdx.y;
    const int r0  = blockIdx.x * 512 + 2 * tid;

    const float* Ob = O + (size_t)b * DS * NO;
    for (int idx = tid; idx < DE * 20; idx += 256) {
        int e = idx / 20, f2 = idx - e * 20;
        float2 w = *(const float2*)(Wr + (size_t)e * 40 + 2 * f2);
        sW[(size_t)e * 20 + f2] = pack2(w.x, w.y);
    }
    if (tid < DE) sbr[tid] = br[tid];

    const float* ps = Rs + (size_t)b * NO * NR + r0;
    const float* pr = Rr + (size_t)b * NO * NR + r0;

    u64 m1[8][2], m2[8][2];
#pragma unroll
    for (int i = 0; i < 8; i++) {
        m1[i][0] = m1[i][1] = 0ull;
        m2[i][0] = m2[i][1] = 0ull;
    }

    const int U = 4;
    float2 as[2][U], ar[2][U];

    for (int c0 = 0; c0 < NO; c0 += OCH) {
        __syncthreads();   // previous chunk's compute done
        // stage O chunk [c0, c0+OCH)
        for (int idx = tid; idx < 8 * OCH; idx += 256) {
            int d2 = idx >> 9, o = idx & (OCH - 1);
            sO[(size_t)o * 8 + d2] = pack2(Ob[(size_t)(2 * d2) * NO + c0 + o],
                                           Ob[(size_t)(2 * d2 + 1) * NO + c0 + o]);
        }
        __syncthreads();

        // prologue prefetch for this chunk
#pragma unroll
        for (int u = 0; u < U; u++) {
            as[0][u] = *(const float2*)(ps + (size_t)(c0 + u) * NR);
            ar[0][u] = *(const float2*)(pr + (size_t)(c0 + u) * NR);
        }
        int buf = 0;
        for (int oo = 0; oo < OCH; oo += U) {
            int nb = buf ^ 1;
            if (oo + U < OCH) {
#pragma unroll
                for (int u = 0; u < U; u++) {
                    as[nb][u] = *(const float2*)(ps + (size_t)(c0 + oo + U + u) * NR);
                    ar[nb][u] = *(const float2*)(pr + (size_t)(c0 + oo + U + u) * NR);
                }
            }
#pragma unroll
            for (int u = 0; u < U; u++) {
                float2 s = as[buf][u];
                float2 t = ar[buf][u];
                u64 s0 = pack2(s.x, s.x), s1 = pack2(s.y, s.y);
                u64 t0 = pack2(t.x, t.x), t1 = pack2(t.y, t.y);
                const ulonglong2* orow = (const ulonglong2*)(sO + (size_t)(oo + u) * 8);
                ulonglong2 q0 = orow[0], q1 = orow[1], q2 = orow[2], q3 = orow[3];
                m1[0][0] = ffma2(q0.x, s0, m1[0][0]);  m1[0][1] = ffma2(q0.x, s1, m1[0][1]);
                m2[0][0] = ffma2(q0.x, t0, m2[0][0]);  m2[0][1] = ffma2(q0.x, t1, m2[0][1]);
                m1[1][0] = ffma2(q0.y, s0, m1[1][0]);  m1[1][1] = ffma2(q0.y, s1, m1[1][1]);
                m2[1][0] = ffma2(q0.y, t0, m2[1][0]);  m2[1][1] = ffma2(q0.y, t1, m2[1][1]);
                m1[2][0] = ffma2(q1.x, s0, m1[2][0]);  m1[2][1] = ffma2(q1.x, s1, m1[2][1]);
                m2[2][0] = ffma2(q1.x, t0, m2[2][0]);  m2[2][1] = ffma2(q1.x, t1, m2[2][1]);
                m1[3][0] = ffma2(q1.y, s0, m1[3][0]);  m1[3][1] = ffma2(q1.y, s1, m1[3][1]);
                m2[3][0] = ffma2(q1.y, t0, m2[3][0]);  m2[3][1] = ffma2(q1.y, t1, m2[3][1]);
                m1[4][0] = ffma2(q2.x, s0, m1[4][0]);  m1[4][1] = ffma2(q2.x, s1, m1[4][1]);
                m2[4][0] = ffma2(q2.x, t0, m2[4][0]);  m2[4][1] = ffma2(q2.x, t1, m2[4][1]);
                m1[5][0] = ffma2(q2.y, s0, m1[5][0]);  m1[5][1] = ffma2(q2.y, s1, m1[5][1]);
                m2[5][0] = ffma2(q2.y, t0, m2[5][0]);  m2[5][1] = ffma2(q2.y, t1, m2[5][1]);
                m1[6][0] = ffma2(q3.x, s0, m1[6][0]);  m1[6][1] = ffma2(q3.x, s1, m1[6][1]);
                m2[6][0] = ffma2(q3.x, t0, m2[6][0]);  m2[6][1] = ffma2(q3.x, t1, m2[6][1]);
                m1[7][0] = ffma2(q3.y, s0, m1[7][0]);  m1[7][1] = ffma2(q3.y, s1, m1[7][1]);
                m2[7][0] = ffma2(q3.y, t0, m2[7][0]);  m2[7][1] = ffma2(q3.y, t1, m2[7][1]);
            }
            buf = nb;
        }
    }

    const float* Rab = Ra + (size_t)b * DR * NR + r0;
    u64 rap[2][4];
#pragma unroll
    for (int c = 0; c < 2; c++)
#pragma unroll
        for (int j = 0; j < 4; j++)
            rap[c][j] = pack2(Rab[(size_t)(2 * j) * NR + c], Rab[(size_t)(2 * j + 1) * NR + c]);

    float* Eb = g_E + (size_t)b * DE * NR + r0;
#pragma unroll 2
    for (int e = 0; e < DE; e++) {
        const u64* wrow = sW + (size_t)e * 20;
        u64 a0 = 0ull, a1 = 0ull;
#pragma unroll
        for (int f2 = 0; f2 < 8; f2++) {
            a0 = ffma2(wrow[f2], m1[f2][0], a0);
            a1 = ffma2(wrow[f2], m1[f2][1], a1);
        }
#pragma unroll
        for (int f2 = 0; f2 < 8; f2++) {
            a0 = ffma2(wrow[8 + f2], m2[f2][0], a0);
            a1 = ffma2(wrow[8 + f2], m2[f2][1], a1);
        }
#pragma unroll
        for (int j = 0; j < 4; j++) {
            a0 = ffma2(wrow[16 + j], rap[0][j], a0);
            a1 = ffma2(wrow[16 + j], rap[1][j], a1);
        }
        float2 v0 = unpack2(a0), v1 = unpack2(a1);
        *(float2*)(Eb + (size_t)e * NR) = make_float2(v0.x + v0.y + sbr[e],
                                                      v1.x + v1.y + sbr[e]);
    }
}

// ============================================================================
// Kernel B: E_hat[z][b][o][e] = sum_{r in z} R_r[b,o,r] * E[b,e,r]
// mma.sync.m16n8k16 bf16 (tensor pipe), 2-limb split, 3 products, fp32 acc.
// CTA 128o x 64e, 8 warps (4x2), KC=32, reg-prefetch.
// grid (16, BATCH, ZB=4) = 256 CTAs -> 2 CTAs/SM for latency hiding.
// ============================================================================
__global__ void __launch_bounds__(256, 2)
kernelB(const float* __restrict__ Rr)
{
    __shared__ __align__(128) char sAh[128 * PITCH];
    __shared__ __align__(128) char sAl[128 * PITCH];
    __shared__ __align__(128) char sBh[64 * PITCH];
    __shared__ __align__(128) char sBl[64 * PITCH];

    const int tid = threadIdx.x;
    const int wid = tid >> 5;
    const int lid = tid & 31;
    const int wm  = wid & 3;
    const int wn  = wid >> 2;
    const int o0  = blockIdx.x * 128;
    const int b   = blockIdx.y;
    const int z   = blockIdx.z;

    const uint32_t uAh = smem_u32(sAh), uAl = smem_u32(sAl);
    const uint32_t uBh = smem_u32(sBh), uBl = smem_u32(sBl);

    const float* Ag = Rr  + (size_t)b * NO * NR + (size_t)z * KZ;   // rows: o
    const float* Bg = g_E + (size_t)b * DE * NR + (size_t)z * KZ;   // rows: e

    const int arow = tid >> 1, akh = (tid & 1) * 16;
    const int brow = tid >> 2, bkq = (tid & 3) * 8;

    const uint32_t a_lrow = (uint32_t)((wm * 32) + (((lid >> 3) & 1) * 8) + (lid & 7));
    const uint32_t a_lcol = (uint32_t)((lid >> 4) * 8);
    const uint32_t b_lrow = (uint32_t)((wn * 32) + (((lid >> 3) >> 1) * 8) + (lid & 7));
    const uint32_t b_lcol = (uint32_t)(((lid >> 3) & 1) * 8);

    float acc[2][4][4];
#pragma unroll
    for (int i = 0; i < 2; i++)
#pragma unroll
        for (int j = 0; j < 4; j++)
#pragma unroll
            for (int v = 0; v < 4; v++) acc[i][j][v] = 0.f;

    float4 av[4], bv[2];
    {
        const float* ap = Ag + (size_t)(o0 + arow) * NR + akh;
#pragma unroll
        for (int q = 0; q < 4; q++) av[q] = *(const float4*)(ap + 4 * q);
        const float* bp = Bg + (size_t)brow * NR + bkq;
#pragma unroll
        for (int q = 0; q < 2; q++) bv[q] = *(const float4*)(bp + 4 * q);
    }

    for (int kc = 0; kc < NCH; kc++) {
        if (kc > 0) __syncthreads();

#pragma unroll
        for (int q = 0; q < 4; q++) {
            uint32_t h0, h1, l0, l1;
            split2(av[q].x, av[q].y, h0, l0);
            split2(av[q].z, av[q].w, h1, l1);
            uint32_t off = (uint32_t)arow * PITCH + (uint32_t)(akh + 4 * q) * 2;
            sts64(uAh + off, h0, h1);
            sts64(uAl + off, l0, l1);
        }
#pragma unroll
        for (int q = 0; q < 2; q++) {
            uint32_t h0, h1, l0, l1;
            split2(bv[q].x, bv[q].y, h0, l0);
            split2(bv[q].z, bv[q].w, h1, l1);
            uint32_t off = (uint32_t)brow * PITCH + (uint32_t)(bkq + 4 * q) * 2;
            sts64(uBh + off, h0, h1);
            sts64(uBl + off, l0, l1);
        }
        __syncthreads();

        if (kc + 1 < NCH) {
            const int rb = (kc + 1) * KC;
            const float* ap = Ag + (size_t)(o0 + arow) * NR + rb + akh;
#pragma unroll
            for (int q = 0; q < 4; q++) av[q] = *(const float4*)(ap + 4 * q);
            const float* bp = Bg + (size_t)brow * NR + rb + bkq;
#pragma unroll
            for (int q = 0; q < 2; q++) bv[q] = *(const float4*)(bp + 4 * q);
        }

#pragma unroll
        for (int ks = 0; ks < 2; ks++) {
            const uint32_t koff = (uint32_t)(ks * 16) * 2;
            uint32_t ah[2][4], al[2][4];
            uint32_t bh[4][2], bl[4][2];
#pragma unroll
            for (int mt = 0; mt < 2; mt++) {
                uint32_t addr = (a_lrow + mt * 16) * PITCH + a_lcol * 2 + koff;
                ldm_x4(ah[mt], uAh + addr);
                ldm_x4(al[mt], uAl + addr);
            }
#pragma unroll
            for (int tp = 0; tp < 2; tp++) {
                uint32_t addr = (b_lrow + tp * 16) * PITCH + b_lcol * 2 + koff;
                uint32_t rh[4], rl[4];
                ldm_x4(rh, uBh + addr);
                ldm_x4(rl, uBl + addr);
                bh[2 * tp][0] = rh[0]; bh[2 * tp][1] = rh[1];
                bh[2 * tp + 1][0] = rh[2]; bh[2 * tp + 1][1] = rh[3];
                bl[2 * tp][0] = rl[0]; bl[2 * tp][1] = rl[1];
                bl[2 * tp + 1][0] = rl[2]; bl[2 * tp + 1][1] = rl[3];
            }
#pragma unroll
            for (int mt = 0; mt < 2; mt++)
#pragma unroll
                for (int nt = 0; nt < 4; nt++) {
                    mma16816(acc[mt][nt], ah[mt], bh[nt]);
                    mma16816(acc[mt][nt], ah[mt], bl[nt]);
                    mma16816(acc[mt][nt], al[mt], bh[nt]);
                }
        }
    }

    float* outb = g_Ehp + ((size_t)(z * BATCH + b) * NO) * DE;
#pragma unroll
    for (int mt = 0; mt < 2; mt++) {
        int o = o0 + wm * 32 + mt * 16 + (lid >> 2);
#pragma unroll
        for (int nt = 0; nt < 4; nt++) {
            int e = wn * 32 + nt * 8 + (lid & 3) * 2;
            float* p = outb + (size_t)o * DE + e;
            *(float2*)p = make_float2(acc[mt][nt][0], acc[mt][nt][1]);
            *(float2*)(p + 8 * DE) = make_float2(acc[mt][nt][2], acc[mt][nt][3]);
        }
    }
}

// ============================================================================
// Kernel C: P = W_o@[O;X;sum_z E_hat_z]+b_o ; scores = W_s@P+b_s ; softmax
// ============================================================================
__global__ void __launch_bounds__(256, 1)
kernelC(const float* __restrict__ O, const float* __restrict__ X,
        const float* __restrict__ Wo, const float* __restrict__ bo,
        const float* __restrict__ Ws, const float* __restrict__ bs,
        float* __restrict__ out)
{
    __shared__ u64 sWo[88 * 32];
    __shared__ u64 sWs[NC * 32];
    __shared__ float sbo[DP];
    __shared__ float sbs[NC];

    const int tid = threadIdx.x;
    const int b   = blockIdx.y;
    const int o   = blockIdx.x * 256 + tid;

    for (int idx = tid; idx < 88 * 32; idx += 256) {
        int f = idx >> 5, p2 = idx & 31;
        sWo[f * 32 + p2] = pack2(Wo[(size_t)(2 * p2) * 88 + f],
                                 Wo[(size_t)(2 * p2 + 1) * 88 + f]);
    }
    for (int idx = tid; idx < NC * 32; idx += 256) {
        int c = idx >> 5, p2 = idx & 31;
        float2 w = *(const float2*)(Ws + (size_t)c * DP + 2 * p2);
        sWs[c * 32 + p2] = pack2(w.x, w.y);
    }
    if (tid < DP) sbo[tid] = bo[tid];
    if (tid < NC) sbs[tid] = bs[tid];
    __syncthreads();

    u64 P[32];
#pragma unroll
    for (int p2 = 0; p2 < 32; p2++) P[p2] = pack2(sbo[2 * p2], sbo[2 * p2 + 1]);

    const float* Ob = O + (size_t)b * DS * NO + o;
    const float* Xb = X + (size_t)b * DX * NO + o;

#pragma unroll 4
    for (int f = 0; f < DS; f++) {
        float cf = Ob[(size_t)f * NO];
        u64 c2 = pack2(cf, cf);
        const u64* wrow = sWo + f * 32;
#pragma unroll
        for (int p2 = 0; p2 < 32; p2++) P[p2] = ffma2(wrow[p2], c2, P[p2]);
    }
#pragma unroll 4
    for (int f = 0; f < DX; f++) {
        float cf = Xb[(size_t)f * NO];
        u64 c2 = pack2(cf, cf);
        const u64* wrow = sWo + (DS + f) * 32;
#pragma unroll
        for (int p2 = 0; p2 < 32; p2++) P[p2] = ffma2(wrow[p2], c2, P[p2]);
    }
    // E_hat: [z][b][o][e], contiguous in e; sum ZB=4 partials
    const float* ep0 = g_Ehp + ((size_t)b * NO + o) * DE;
    const size_t SSTR = (size_t)BATCH * NO * DE;
#pragma unroll 4
    for (int f4 = 0; f4 < 16; f4++) {
        float4 v0 = *(const float4*)(ep0 + 4 * f4);
        float4 v1 = *(const float4*)(ep0 + SSTR + 4 * f4);
        float4 v2 = *(const float4*)(ep0 + 2 * SSTR + 4 * f4);
        float4 v3 = *(const float4*)(ep0 + 3 * SSTR + 4 * f4);
        float cf[4] = {(v0.x + v1.x) + (v2.x + v3.x),
                       (v0.y + v1.y) + (v2.y + v3.y),
                       (v0.z + v1.z) + (v2.z + v3.z),
                       (v0.w + v1.w) + (v2.w + v3.w)};
#pragma unroll
        for (int j = 0; j < 4; j++) {
            u64 c2 = pack2(cf[j], cf[j]);
            const u64* wrow = sWo + (DS + DX + 4 * f4 + j) * 32;
#pragma unroll
            for (int p2 = 0; p2 < 32; p2++) P[p2] = ffma2(wrow[p2], c2, P[p2]);
        }
    }

    float sc[NC];
#pragma unroll
    for (int c = 0; c < NC; c++) {
        const u64* wrow = sWs + c * 32;
        u64 acc = 0ull;
#pragma unroll
        for (int p2 = 0; p2 < 32; p2++) acc = ffma2(wrow[p2], P[p2], acc);
        float2 a = unpack2(acc);
        sc[c] = a.x + a.y + sbs[c];
    }

    float mx = sc[0];
#pragma unroll
    for (int c = 1; c < NC; c++) mx = fmaxf(mx, sc[c]);
    float sum = 0.f;
#pragma unroll
    for (int c = 0; c < NC; c++) { sc[c] = expf(sc[c] - mx); sum += sc[c]; }
    float inv = 1.f / sum;
#pragma unroll
    for (int c = 0; c < NC; c++)
        out[((size_t)b * NC + c) * NO + o] = sc[c] * inv;
}

// ============================================================================
extern "C" void kernel_launch(void* const* d_in, const int* in_sizes, int n_in,
                              void* d_out, int out_size)
{
    const float* O  = (const float*)d_in[0];
    const float* Rs = (const float*)d_in[1];
    const float* Rr = (const float*)d_in[2];
    const float* Ra = (const float*)d_in[3];
    const float* X  = (const float*)d_in[4];
    const float* Wr = (const float*)d_in[5];
    const float* br = (const float*)d_in[6];
    const float* Wo = (const float*)d_in[7];
    const float* bo = (const float*)d_in[8];
    const float* Ws = (const float*)d_in[9];
    const float* bs = (const float*)d_in[10];
    float* out = (float*)d_out;
    (void)in_sizes; (void)n_in; (void)out_size;

    int smA = OCH * 8 * 8 + DE * 20 * 8 + DE * 4;   // 43264 B
    cudaFuncSetAttribute(kernelA, cudaFuncAttributeMaxDynamicSharedMemorySize, smA);

    kernelA<<<dim3(NR / 512, BATCH), 256, smA>>>(O, Rs, Rr, Ra, Wr, br);
    kernelB<<<dim3(NO / 128, BATCH, ZB), 256>>>(Rr);
    kernelC<<<dim3(NO / 256, BATCH), 256>>>(O, X, Wo, bo, Ws, bs, out);
}

// round 9
// speedup vs baseline: 2.4275x; 1.4016x over previous
#include <cuda_runtime.h>
#include <cstdint>

#define BATCH 4
#define DS 16
#define NO 2048
#define NR 16384
#define DR 8
#define DE 64
#define DX 8
#define DP 64
#define NC 10

// kernelA tiling (HMMA GEMM over o)
#define RT 256              // r per CTA
#define KCA 16              // o per chunk
#define NCHA (NO / KCA)     // 128 chunks
#define PITA 528            // stage tile o-row pitch bytes (33*16 -> LDSM conflict-free)
#define OPIT 48             // O tile d-row pitch bytes (3*16 -> conflict-free)

// kernelB tiling
#define ZB 4
#define KZ (NR / ZB)        // 4096 r per z-split
#define KC 32               // r per chunk
#define NCH (KZ / KC)       // 128 chunks
#define PITCH 80            // smem row pitch bytes

typedef unsigned long long u64;
typedef unsigned short u16;

// Scratch (allocation-free rule: __device__ globals)
__device__ u16  g_Ehi[(size_t)BATCH * DE * NR];        // 8.4 MB  E hi limb (bf16 bits)
__device__ u16  g_Elo[(size_t)BATCH * DE * NR];        // 8.4 MB  E lo limb
__device__ float g_Ehp[(size_t)ZB * BATCH * NO * DE];  // 8.4 MB  partials [z][b][o][e]

// ---- packed fp32x2 helpers (FFMA2) ----
__device__ __forceinline__ u64 ffma2(u64 a, u64 b, u64 c) {
    u64 d;
    asm("fma.rn.f32x2 %0, %1, %2, %3;" : "=l"(d) : "l"(a), "l"(b), "l"(c));
    return d;
}
__device__ __forceinline__ u64 pack2(float lo, float hi) {
    u64 r;
    asm("mov.b64 %0, {%1, %2};" : "=l"(r) : "f"(lo), "f"(hi));
    return r;
}
__device__ __forceinline__ float2 unpack2(u64 v) {
    float2 f;
    asm("mov.b64 {%0, %1}, %2;" : "=f"(f.x), "=f"(f.y) : "l"(v));
    return f;
}
__device__ __forceinline__ uint32_t smem_u32(const void* p) {
    uint32_t a;
    asm("{ .reg .u64 t; cvta.to.shared.u64 t, %1; cvt.u32.u64 %0, t; }" : "=r"(a) : "l"(p));
    return a;
}
// split (x0,x1) -> packed bf16x2 hi limb + packed bf16x2 lo residual (x0 in LOW half)
__device__ __forceinline__ void split2(float x0, float x1, uint32_t& hi, uint32_t& lo) {
    asm("cvt.rn.bf16x2.f32 %0, %1, %2;" : "=r"(hi) : "f"(x1), "f"(x0));
    float h0 = __uint_as_float(hi << 16);
    float h1 = __uint_as_float(hi & 0xFFFF0000u);
    float r0 = x0 - h0, r1 = x1 - h1;
    asm("cvt.rn.bf16x2.f32 %0, %1, %2;" : "=r"(lo) : "f"(r1), "f"(r0));
}
__device__ __forceinline__ void sts64(uint32_t a, uint32_t x, uint32_t y) {
    asm volatile("st.shared.v2.b32 [%0], {%1,%2};" :: "r"(a), "r"(x), "r"(y) : "memory");
}
__device__ __forceinline__ void sts128(uint32_t a, uint32_t x, uint32_t y, uint32_t z, uint32_t w) {
    asm volatile("st.shared.v4.b32 [%0], {%1,%2,%3,%4};" :: "r"(a), "r"(x), "r"(y), "r"(z), "r"(w) : "memory");
}
__device__ __forceinline__ void ldm_x4(uint32_t* r, uint32_t addr) {
    asm volatile("ldmatrix.sync.aligned.m8n8.x4.shared.b16 {%0,%1,%2,%3}, [%4];"
                 : "=r"(r[0]), "=r"(r[1]), "=r"(r[2]), "=r"(r[3]) : "r"(addr));
}
__device__ __forceinline__ void ldm_x4t(uint32_t* r, uint32_t addr) {
    asm volatile("ldmatrix.sync.aligned.m8n8.x4.trans.shared.b16 {%0,%1,%2,%3}, [%4];"
                 : "=r"(r[0]), "=r"(r[1]), "=r"(r[2]), "=r"(r[3]) : "r"(addr));
}
__device__ __forceinline__ void mma16816(float* d, const uint32_t* a, const uint32_t* b) {
    asm volatile(
        "mma.sync.aligned.m16n8k16.row.col.f32.bf16.bf16.f32 "
        "{%0,%1,%2,%3}, {%4,%5,%6,%7}, {%8,%9}, {%0,%1,%2,%3};"
        : "+f"(d[0]), "+f"(d[1]), "+f"(d[2]), "+f"(d[3])
        : "r"(a[0]), "r"(a[1]), "r"(a[2]), "r"(a[3]), "r"(b[0]), "r"(b[1]));
}

// ============================================================================
// Kernel A: M1/M2 via HMMA (D[r,d] = sum_o Rs/Rr[o,r] * O[d,o]), then
// E = W_r @ [M1;M2;Ra] + b_r in a per-thread FFMA2 epilogue; E written as
// bf16 hi/lo limbs for kernelB. grid (NR/256, BATCH) = 256 CTAs, block 256.
// A-operand (R) via ldmatrix.trans from [o][r] tiles; B-operand (O) non-trans
// from [d][o] tiles (same pattern as the passing kernelB E-side).
// ============================================================================
__global__ void __launch_bounds__(256, 2)
kernelA(const float* __restrict__ O, const float* __restrict__ Rs,
        const float* __restrict__ Rr, const float* __restrict__ Ra,
        const float* __restrict__ Wr, const float* __restrict__ br)
{
    __shared__ __align__(16) char sStage[34816];          // 4 R-tiles (33792) / sM (34816)
    __shared__ __align__(16) char sOt[2 * DS * OPIT];     // O hi/lo tiles (1536)
    __shared__ u64 sW[DE * 20];
    __shared__ float sbr[DE];

    const int tid = threadIdx.x;
    const int wid = tid >> 5;
    const int lid = tid & 31;
    const int b   = blockIdx.y;
    const int r0  = blockIdx.x * RT;

    const uint32_t uSt  = smem_u32(sStage);
    const uint32_t uRsH = uSt, uRsL = uSt + 8448, uRrH = uSt + 16896, uRrL = uSt + 25344;
    const uint32_t uOH  = smem_u32(sOt);

    for (int idx = tid; idx < DE * 20; idx += 256) {
        int e = idx / 20, f2 = idx - e * 20;
        float2 w = *(const float2*)(Wr + (size_t)e * 40 + 2 * f2);
        sW[e * 20 + f2] = pack2(w.x, w.y);
    }
    if (tid < DE) sbr[tid] = br[tid];

    const float* Rsb = Rs + (size_t)b * NO * NR + r0;
    const float* Rrb = Rr + (size_t)b * NO * NR + r0;
    const float* Ob  = O  + (size_t)b * DS * NO;

    float accS[2][2][4], accR[2][2][4];
#pragma unroll
    for (int i = 0; i < 2; i++)
#pragma unroll
        for (int j = 0; j < 2; j++)
#pragma unroll
            for (int v = 0; v < 4; v++) { accS[i][j][v] = 0.f; accR[i][j][v] = 0.f; }

    // staging maps
    const int so = tid >> 6;     // o sub-row 0..3 (per q: o = q*4 + so)
    const int c4 = tid & 63;     // r float4 index
    const int od = tid >> 4;     // O: d row
    const int oo = tid & 15;     // O: o col

    // ldmatrix lane maps
    const uint32_t krow = (uint32_t)((lid & 7) + ((lid >> 4) << 3));   // trans A: k row
    const uint32_t mcol = (uint32_t)(((lid >> 3) & 1) << 3);           // trans A: m offset
    const uint32_t brow_ = (uint32_t)(((lid >> 4) << 3) + (lid & 7));  // O: d row
    const uint32_t bcol_ = (uint32_t)(((lid >> 3) & 1) << 3);          // O: o offset

    float4 pS[4], pR[4];
    float  pO;

#define LOADA(cb) do {                                                        \
    _Pragma("unroll")                                                         \
    for (int q = 0; q < 4; q++) {                                             \
        size_t row = (size_t)((cb) + q * 4 + so) * NR;                        \
        pS[q] = *(const float4*)(Rsb + row + c4 * 4);                         \
        pR[q] = *(const float4*)(Rrb + row + c4 * 4);                         \
    }                                                                         \
    pO = Ob[(size_t)od * NO + (cb) + oo];                                     \
} while (0)

    LOADA(0);

    for (int kc = 0; kc < NCHA; kc++) {
        __syncthreads();   // previous chunk's compute done

        // convert + store tiles
#pragma unroll
        for (int q = 0; q < 4; q++) {
            uint32_t h0, l0, h1, l1;
            uint32_t off = (uint32_t)(q * 4 + so) * PITA + (uint32_t)c4 * 8;
            split2(pS[q].x, pS[q].y, h0, l0);
            split2(pS[q].z, pS[q].w, h1, l1);
            sts64(uRsH + off, h0, h1);
            sts64(uRsL + off, l0, l1);
            split2(pR[q].x, pR[q].y, h0, l0);
            split2(pR[q].z, pR[q].w, h1, l1);
            sts64(uRrH + off, h0, h1);
            sts64(uRrL + off, l0, l1);
        }
        {
            uint32_t h32, l32;
            split2(pO, 0.f, h32, l32);
            *(u16*)(sOt + od * OPIT + oo * 2)                 = (u16)h32;
            *(u16*)(sOt + DS * OPIT + od * OPIT + oo * 2)     = (u16)l32;
        }
        __syncthreads();

        if (kc + 1 < NCHA) LOADA((kc + 1) * KCA);

        // compute chunk (one k-step of 16 o)
        uint32_t bOh[4], bOl[4];
        {
            uint32_t oaddr = uOH + brow_ * OPIT + bcol_ * 2;
            ldm_x4(bOh, oaddr);
            ldm_x4(bOl, oaddr + DS * OPIT);
        }
#pragma unroll
        for (int mt = 0; mt < 2; mt++) {
            uint32_t aoff = krow * PITA + (uint32_t)(wid * 32 + mt * 16) * 2 + mcol * 2;
            uint32_t ash[4], asl[4], arh[4], arl[4];
            ldm_x4t(ash, uRsH + aoff);
            ldm_x4t(asl, uRsL + aoff);
            ldm_x4t(arh, uRrH + aoff);
            ldm_x4t(arl, uRrL + aoff);
#pragma unroll
            for (int nt = 0; nt < 2; nt++) {
                mma16816(accS[mt][nt], ash, bOh + nt * 2);
                mma16816(accS[mt][nt], ash, bOl + nt * 2);
                mma16816(accS[mt][nt], asl, bOh + nt * 2);
                mma16816(accR[mt][nt], arh, bOh + nt * 2);
                mma16816(accR[mt][nt], arh, bOl + nt * 2);
                mma16816(accR[mt][nt], arl, bOh + nt * 2);
            }
        }
    }
#undef LOADA

    // ---- epilogue: frags -> sM[r][32 feats], then E per thread ----
    __syncthreads();
    float* sM = (float*)sStage;    // [256][34] floats
#pragma unroll
    for (int mt = 0; mt < 2; mt++) {
        int rl = wid * 32 + mt * 16 + (lid >> 2);
#pragma unroll
        for (int nt = 0; nt < 2; nt++) {
            int c = nt * 8 + (lid & 3) * 2;
            *(float2*)(sM + rl * 34 + c)            = make_float2(accS[mt][nt][0], accS[mt][nt][1]);
            *(float2*)(sM + (rl + 8) * 34 + c)      = make_float2(accS[mt][nt][2], accS[mt][nt][3]);
            *(float2*)(sM + rl * 34 + 16 + c)       = make_float2(accR[mt][nt][0], accR[mt][nt][1]);
            *(float2*)(sM + (rl + 8) * 34 + 16 + c) = make_float2(accR[mt][nt][2], accR[mt][nt][3]);
        }
    }
    __syncthreads();

    const int r = tid;
    u64 mp[16];
    const u64* mrow = (const u64*)(sM + r * 34);
#pragma unroll
    for (int j = 0; j < 16; j++) mp[j] = mrow[j];

    const float* Rab = Ra + (size_t)b * DR * NR + r0 + r;
    u64 rap[4];
#pragma unroll
    for (int j = 0; j < 4; j++)
        rap[j] = pack2(Rab[(size_t)(2 * j) * NR], Rab[(size_t)(2 * j + 1) * NR]);

    u16* EH = g_Ehi + (size_t)b * DE * NR + r0 + r;
    u16* EL = g_Elo + (size_t)b * DE * NR + r0 + r;
#pragma unroll 2
    for (int e = 0; e < DE; e++) {
        const u64* wrow = sW + e * 20;
        u64 a = 0ull;
#pragma unroll
        for (int j = 0; j < 16; j++) a = ffma2(wrow[j], mp[j], a);
#pragma unroll
        for (int j = 0; j < 4; j++)  a = ffma2(wrow[16 + j], rap[j], a);
        float2 v = unpack2(a);
        float val = v.x + v.y + sbr[e];
        uint32_t h32, l32;
        split2(val, 0.f, h32, l32);
        EH[(size_t)e * NR] = (u16)h32;
        EL[(size_t)e * NR] = (u16)l32;
    }
}

// ============================================================================
// Kernel B: E_hat[z][b][o][e] = sum_{r in z} R_r[b,o,r] * E[b,e,r]
// mma.sync bf16, 3 limb products. E arrives pre-split (bf16 hi/lo) -> B-side
// staging is a straight uint4 copy. grid (16, BATCH, ZB=4) = 256 CTAs.
// ============================================================================
__global__ void __launch_bounds__(256, 2)
kernelB(const float* __restrict__ Rr)
{
    __shared__ __align__(128) char sAh[128 * PITCH];
    __shared__ __align__(128) char sAl[128 * PITCH];
    __shared__ __align__(128) char sBh[64 * PITCH];
    __shared__ __align__(128) char sBl[64 * PITCH];

    const int tid = threadIdx.x;
    const int wid = tid >> 5;
    const int lid = tid & 31;
    const int wm  = wid & 3;
    const int wn  = wid >> 2;
    const int o0  = blockIdx.x * 128;
    const int b   = blockIdx.y;
    const int z   = blockIdx.z;

    const uint32_t uAh = smem_u32(sAh), uAl = smem_u32(sAl);
    const uint32_t uBh = smem_u32(sBh), uBl = smem_u32(sBl);

    const float* Ag  = Rr    + (size_t)b * NO * NR + (size_t)z * KZ;
    const u16*   BgH = g_Ehi + (size_t)b * DE * NR + (size_t)z * KZ;
    const u16*   BgL = g_Elo + (size_t)b * DE * NR + (size_t)z * KZ;

    const int arow = tid >> 1, akh = (tid & 1) * 16;
    const int brow = tid >> 2, bkq = (tid & 3) * 8;

    const uint32_t a_lrow = (uint32_t)((wm * 32) + (((lid >> 3) & 1) * 8) + (lid & 7));
    const uint32_t a_lcol = (uint32_t)((lid >> 4) * 8);
    const uint32_t b_lrow = (uint32_t)((wn * 32) + (((lid >> 3) >> 1) * 8) + (lid & 7));
    const uint32_t b_lcol = (uint32_t)(((lid >> 3) & 1) * 8);

    float acc[2][4][4];
#pragma unroll
    for (int i = 0; i < 2; i++)
#pragma unroll
        for (int j = 0; j < 4; j++)
#pragma unroll
            for (int v = 0; v < 4; v++) acc[i][j][v] = 0.f;

    float4 av[4];
    uint4  bvh, bvl;
    {
        const float* ap = Ag + (size_t)(o0 + arow) * NR + akh;
#pragma unroll
        for (int q = 0; q < 4; q++) av[q] = *(const float4*)(ap + 4 * q);
        bvh = *(const uint4*)(BgH + (size_t)brow * NR + bkq);
        bvl = *(const uint4*)(BgL + (size_t)brow * NR + bkq);
    }

    for (int kc = 0; kc < NCH; kc++) {
        if (kc > 0) __syncthreads();

#pragma unroll
        for (int q = 0; q < 4; q++) {
            uint32_t h0, h1, l0, l1;
            split2(av[q].x, av[q].y, h0, l0);
            split2(av[q].z, av[q].w, h1, l1);
            uint32_t off = (uint32_t)arow * PITCH + (uint32_t)(akh + 4 * q) * 2;
            sts64(uAh + off, h0, h1);
            sts64(uAl + off, l0, l1);
        }
        {
            uint32_t off = (uint32_t)brow * PITCH + (uint32_t)bkq * 2;
            sts128(uBh + off, bvh.x, bvh.y, bvh.z, bvh.w);
            sts128(uBl + off, bvl.x, bvl.y, bvl.z, bvl.w);
        }
        __syncthreads();

        if (kc + 1 < NCH) {
            const int rb = (kc + 1) * KC;
            const float* ap = Ag + (size_t)(o0 + arow) * NR + rb + akh;
#pragma unroll
            for (int q = 0; q < 4; q++) av[q] = *(const float4*)(ap + 4 * q);
            bvh = *(const uint4*)(BgH + (size_t)brow * NR + rb + bkq);
            bvl = *(const uint4*)(BgL + (size_t)brow * NR + rb + bkq);
        }

#pragma unroll
        for (int ks = 0; ks < 2; ks++) {
            const uint32_t koff = (uint32_t)(ks * 16) * 2;
            uint32_t ah[2][4], al[2][4];
            uint32_t bh[4][2], bl[4][2];
#pragma unroll
            for (int mt = 0; mt < 2; mt++) {
                uint32_t addr = (a_lrow + mt * 16) * PITCH + a_lcol * 2 + koff;
                ldm_x4(ah[mt], uAh + addr);
                ldm_x4(al[mt], uAl + addr);
            }
#pragma unroll
            for (int tp = 0; tp < 2; tp++) {
                uint32_t addr = (b_lrow + tp * 16) * PITCH + b_lcol * 2 + koff;
                uint32_t rh[4], rl[4];
                ldm_x4(rh, uBh + addr);
                ldm_x4(rl, uBl + addr);
                bh[2 * tp][0] = rh[0]; bh[2 * tp][1] = rh[1];
                bh[2 * tp + 1][0] = rh[2]; bh[2 * tp + 1][1] = rh[3];
                bl[2 * tp][0] = rl[0]; bl[2 * tp][1] = rl[1];
                bl[2 * tp + 1][0] = rl[2]; bl[2 * tp + 1][1] = rl[3];
            }
#pragma unroll
            for (int mt = 0; mt < 2; mt++)
#pragma unroll
                for (int nt = 0; nt < 4; nt++) {
                    mma16816(acc[mt][nt], ah[mt], bh[nt]);
                    mma16816(acc[mt][nt], ah[mt], bl[nt]);
                    mma16816(acc[mt][nt], al[mt], bh[nt]);
                }
        }
    }

    float* outb = g_Ehp + ((size_t)(z * BATCH + b) * NO) * DE;
#pragma unroll
    for (int mt = 0; mt < 2; mt++) {
        int o = o0 + wm * 32 + mt * 16 + (lid >> 2);
#pragma unroll
        for (int nt = 0; nt < 4; nt++) {
            int e = wn * 32 + nt * 8 + (lid & 3) * 2;
            float* p = outb + (size_t)o * DE + e;
            *(float2*)p = make_float2(acc[mt][nt][0], acc[mt][nt][1]);
            *(float2*)(p + 8 * DE) = make_float2(acc[mt][nt][2], acc[mt][nt][3]);
        }
    }
}

// ============================================================================
// Kernel C: P = W_o@[O;X;sum_z E_hat_z]+b_o ; scores = W_s@P+b_s ; softmax
// ============================================================================
__global__ void __launch_bounds__(256, 1)
kernelC(const float* __restrict__ O, const float* __restrict__ X,
        const float* __restrict__ Wo, const float* __restrict__ bo,
        const float* __restrict__ Ws, const float* __restrict__ bs,
        float* __restrict__ out)
{
    __shared__ u64 sWo[88 * 32];
    __shared__ u64 sWs[NC * 32];
    __shared__ float sbo[DP];
    __shared__ float sbs[NC];

    const int tid = threadIdx.x;
    const int b   = blockIdx.y;
    const int o   = blockIdx.x * 256 + tid;

    for (int idx = tid; idx < 88 * 32; idx += 256) {
        int f = idx >> 5, p2 = idx & 31;
        sWo[f * 32 + p2] = pack2(Wo[(size_t)(2 * p2) * 88 + f],
                                 Wo[(size_t)(2 * p2 + 1) * 88 + f]);
    }
    for (int idx = tid; idx < NC * 32; idx += 256) {
        int c = idx >> 5, p2 = idx & 31;
        float2 w = *(const float2*)(Ws + (size_t)c * DP + 2 * p2);
        sWs[c * 32 + p2] = pack2(w.x, w.y);
    }
    if (tid < DP) sbo[tid] = bo[tid];
    if (tid < NC) sbs[tid] = bs[tid];
    __syncthreads();

    u64 P[32];
#pragma unroll
    for (int p2 = 0; p2 < 32; p2++) P[p2] = pack2(sbo[2 * p2], sbo[2 * p2 + 1]);

    const float* Ob = O + (size_t)b * DS * NO + o;
    const float* Xb = X + (size_t)b * DX * NO + o;

#pragma unroll 4
    for (int f = 0; f < DS; f++) {
        float cf = Ob[(size_t)f * NO];
        u64 c2 = pack2(cf, cf);
        const u64* wrow = sWo + f * 32;
#pragma unroll
        for (int p2 = 0; p2 < 32; p2++) P[p2] = ffma2(wrow[p2], c2, P[p2]);
    }
#pragma unroll 4
    for (int f = 0; f < DX; f++) {
        float cf = Xb[(size_t)f * NO];
        u64 c2 = pack2(cf, cf);
        const u64* wrow = sWo + (DS + f) * 32;
#pragma unroll
        for (int p2 = 0; p2 < 32; p2++) P[p2] = ffma2(wrow[p2], c2, P[p2]);
    }
    const float* ep0 = g_Ehp + ((size_t)b * NO + o) * DE;
    const size_t SSTR = (size_t)BATCH * NO * DE;
#pragma unroll 4
    for (int f4 = 0; f4 < 16; f4++) {
        float4 v0 = *(const float4*)(ep0 + 4 * f4);
        float4 v1 = *(const float4*)(ep0 + SSTR + 4 * f4);
        float4 v2 = *(const float4*)(ep0 + 2 * SSTR + 4 * f4);
        float4 v3 = *(const float4*)(ep0 + 3 * SSTR + 4 * f4);
        float cf[4] = {(v0.x + v1.x) + (v2.x + v3.x),
                       (v0.y + v1.y) + (v2.y + v3.y),
                       (v0.z + v1.z) + (v2.z + v3.z),
                       (v0.w + v1.w) + (v2.w + v3.w)};
#pragma unroll
        for (int j = 0; j < 4; j++) {
            u64 c2 = pack2(cf[j], cf[j]);
            const u64* wrow = sWo + (DS + DX + 4 * f4 + j) * 32;
#pragma unroll
            for (int p2 = 0; p2 < 32; p2++) P[p2] = ffma2(wrow[p2], c2, P[p2]);
        }
    }

    float sc[NC];
#pragma unroll
    for (int c = 0; c < NC; c++) {
        const u64* wrow = sWs + c * 32;
        u64 acc = 0ull;
#pragma unroll
        for (int p2 = 0; p2 < 32; p2++) acc = ffma2(wrow[p2], P[p2], acc);
        float2 a = unpack2(acc);
        sc[c] = a.x + a.y + sbs[c];
    }

    float mx = sc[0];
#pragma unroll
    for (int c = 1; c < NC; c++) mx = fmaxf(mx, sc[c]);
    float sum = 0.f;
#pragma unroll
    for (int c = 0; c < NC; c++) { sc[c] = expf(sc[c] - mx); sum += sc[c]; }
    float inv = 1.f / sum;
#pragma unroll
    for (int c = 0; c < NC; c++)
        out[((size_t)b * NC + c) * NO + o] = sc[c] * inv;
}

// ============================================================================
extern "C" void kernel_launch(void* const* d_in, const int* in_sizes, int n_in,
                              void* d_out, int out_size)
{
    const float* O  = (const float*)d_in[0];
    const float* Rs = (const float*)d_in[1];
    const float* Rr = (const float*)d_in[2];
    const float* Ra = (const float*)d_in[3];
    const float* X  = (const float*)d_in[4];
    const float* Wr = (const float*)d_in[5];
    const float* br = (const float*)d_in[6];
    const float* Wo = (const float*)d_in[7];
    const float* bo = (const float*)d_in[8];
    const float* Ws = (const float*)d_in[9];
    const float* bs = (const float*)d_in[10];
    float* out = (float*)d_out;
    (void)in_sizes; (void)n_in; (void)out_size;

    kernelA<<<dim3(NR / RT, BATCH), 256>>>(O, Rs, Rr, Ra, Wr, br);
    kernelB<<<dim3(NO / 128, BATCH, ZB), 256>>>(Rr);
    kernelC<<<dim3(NO / 256, BATCH), 256>>>(O, X, Wo, bo, Ws, bs, out);
}

// round 10
// speedup vs baseline: 2.4909x; 1.0261x over previous
#include <cuda_runtime.h>
#include <cstdint>

#define BATCH 4
#define DS 16
#define NO 2048
#define NR 16384
#define DR 8
#define DE 64
#define DX 8
#define DP 64
#define NC 10

// kernelA tiling (HMMA GEMM over o)
#define RT 256              // r per CTA
#define KCA 16              // o per chunk
#define NCHA (NO / KCA)     // 128 chunks
#define PITA 528            // stage tile o-row pitch bytes
#define OPIT 48             // O tile d-row pitch bytes

// kernelB tiling
#define ZB 4
#define KZ (NR / ZB)        // 4096 r per z-split
#define KC 32               // r per chunk
#define NCH (KZ / KC)       // 128 chunks
#define PITCH 80            // smem row pitch bytes
// kernelB smem layout (per buffer): Ah 10240 | Al 10240 | Bh 5120 | Bl 5120
#define BOF_AL 10240
#define BOF_BH 20480
#define BOF_BL 25600
#define BUFSZ  30720

typedef unsigned long long u64;
typedef unsigned short u16;

// Scratch (allocation-free rule: __device__ globals)
__device__ u16  g_Ehi[(size_t)BATCH * DE * NR];        // 8.4 MB  E hi limb (bf16 bits)
__device__ u16  g_Elo[(size_t)BATCH * DE * NR];        // 8.4 MB  E lo limb
__device__ float g_Ehp[(size_t)ZB * BATCH * NO * DE];  // 8.4 MB  partials [z][b][o][e]

// ---- packed fp32x2 helpers (FFMA2) ----
__device__ __forceinline__ u64 ffma2(u64 a, u64 b, u64 c) {
    u64 d;
    asm("fma.rn.f32x2 %0, %1, %2, %3;" : "=l"(d) : "l"(a), "l"(b), "l"(c));
    return d;
}
__device__ __forceinline__ u64 pack2(float lo, float hi) {
    u64 r;
    asm("mov.b64 %0, {%1, %2};" : "=l"(r) : "f"(lo), "f"(hi));
    return r;
}
__device__ __forceinline__ float2 unpack2(u64 v) {
    float2 f;
    asm("mov.b64 {%0, %1}, %2;" : "=f"(f.x), "=f"(f.y) : "l"(v));
    return f;
}
__device__ __forceinline__ uint32_t smem_u32(const void* p) {
    uint32_t a;
    asm("{ .reg .u64 t; cvta.to.shared.u64 t, %1; cvt.u32.u64 %0, t; }" : "=r"(a) : "l"(p));
    return a;
}
// split (x0,x1) -> packed bf16x2 hi limb + packed bf16x2 lo residual (x0 in LOW half)
__device__ __forceinline__ void split2(float x0, float x1, uint32_t& hi, uint32_t& lo) {
    asm("cvt.rn.bf16x2.f32 %0, %1, %2;" : "=r"(hi) : "f"(x1), "f"(x0));
    float h0 = __uint_as_float(hi << 16);
    float h1 = __uint_as_float(hi & 0xFFFF0000u);
    float r0 = x0 - h0, r1 = x1 - h1;
    asm("cvt.rn.bf16x2.f32 %0, %1, %2;" : "=r"(lo) : "f"(r1), "f"(r0));
}
__device__ __forceinline__ void sts64(uint32_t a, uint32_t x, uint32_t y) {
    asm volatile("st.shared.v2.b32 [%0], {%1,%2};" :: "r"(a), "r"(x), "r"(y) : "memory");
}
__device__ __forceinline__ void sts128(uint32_t a, uint32_t x, uint32_t y, uint32_t z, uint32_t w) {
    asm volatile("st.shared.v4.b32 [%0], {%1,%2,%3,%4};" :: "r"(a), "r"(x), "r"(y), "r"(z), "r"(w) : "memory");
}
__device__ __forceinline__ void ldm_x4(uint32_t* r, uint32_t addr) {
    asm volatile("ldmatrix.sync.aligned.m8n8.x4.shared.b16 {%0,%1,%2,%3}, [%4];"
                 : "=r"(r[0]), "=r"(r[1]), "=r"(r[2]), "=r"(r[3]) : "r"(addr));
}
__device__ __forceinline__ void ldm_x4t(uint32_t* r, uint32_t addr) {
    asm volatile("ldmatrix.sync.aligned.m8n8.x4.trans.shared.b16 {%0,%1,%2,%3}, [%4];"
                 : "=r"(r[0]), "=r"(r[1]), "=r"(r[2]), "=r"(r[3]) : "r"(addr));
}
__device__ __forceinline__ void mma16816(float* d, const uint32_t* a, const uint32_t* b) {
    asm volatile(
        "mma.sync.aligned.m16n8k16.row.col.f32.bf16.bf16.f32 "
        "{%0,%1,%2,%3}, {%4,%5,%6,%7}, {%8,%9}, {%0,%1,%2,%3};"
        : "+f"(d[0]), "+f"(d[1]), "+f"(d[2]), "+f"(d[3])
        : "r"(a[0]), "r"(a[1]), "r"(a[2]), "r"(a[3]), "r"(b[0]), "r"(b[1]));
}

// ============================================================================
// Kernel A: M1/M2 via HMMA, E = W_r@[M1;M2;Ra]+b_r epilogue, E out as bf16
// hi/lo limbs. grid (NR/256, BATCH) = 256 CTAs, block 256.  (R9: 179us, 76% DRAM)
// ============================================================================
__global__ void __launch_bounds__(256, 2)
kernelA(const float* __restrict__ O, const float* __restrict__ Rs,
        const float* __restrict__ Rr, const float* __restrict__ Ra,
        const float* __restrict__ Wr, const float* __restrict__ br)
{
    __shared__ __align__(16) char sStage[34816];
    __shared__ __align__(16) char sOt[2 * DS * OPIT];
    __shared__ u64 sW[DE * 20];
    __shared__ float sbr[DE];

    const int tid = threadIdx.x;
    const int wid = tid >> 5;
    const int lid = tid & 31;
    const int b   = blockIdx.y;
    const int r0  = blockIdx.x * RT;

    const uint32_t uSt  = smem_u32(sStage);
    const uint32_t uRsH = uSt, uRsL = uSt + 8448, uRrH = uSt + 16896, uRrL = uSt + 25344;
    const uint32_t uOH  = smem_u32(sOt);

    for (int idx = tid; idx < DE * 20; idx += 256) {
        int e = idx / 20, f2 = idx - e * 20;
        float2 w = *(const float2*)(Wr + (size_t)e * 40 + 2 * f2);
        sW[e * 20 + f2] = pack2(w.x, w.y);
    }
    if (tid < DE) sbr[tid] = br[tid];

    const float* Rsb = Rs + (size_t)b * NO * NR + r0;
    const float* Rrb = Rr + (size_t)b * NO * NR + r0;
    const float* Ob  = O  + (size_t)b * DS * NO;

    float accS[2][2][4], accR[2][2][4];
#pragma unroll
    for (int i = 0; i < 2; i++)
#pragma unroll
        for (int j = 0; j < 2; j++)
#pragma unroll
            for (int v = 0; v < 4; v++) { accS[i][j][v] = 0.f; accR[i][j][v] = 0.f; }

    const int so = tid >> 6;
    const int c4 = tid & 63;
    const int od = tid >> 4;
    const int oo = tid & 15;

    const uint32_t krow = (uint32_t)((lid & 7) + ((lid >> 4) << 3));
    const uint32_t mcol = (uint32_t)(((lid >> 3) & 1) << 3);
    const uint32_t brow_ = (uint32_t)(((lid >> 4) << 3) + (lid & 7));
    const uint32_t bcol_ = (uint32_t)(((lid >> 3) & 1) << 3);

    float4 pS[4], pR[4];
    float  pO;

#define LOADA(cb) do {                                                        \
    _Pragma("unroll")                                                         \
    for (int q = 0; q < 4; q++) {                                             \
        size_t row = (size_t)((cb) + q * 4 + so) * NR;                        \
        pS[q] = *(const float4*)(Rsb + row + c4 * 4);                         \
        pR[q] = *(const float4*)(Rrb + row + c4 * 4);                         \
    }                                                                         \
    pO = Ob[(size_t)od * NO + (cb) + oo];                                     \
} while (0)

    LOADA(0);

    for (int kc = 0; kc < NCHA; kc++) {
        __syncthreads();

#pragma unroll
        for (int q = 0; q < 4; q++) {
            uint32_t h0, l0, h1, l1;
            uint32_t off = (uint32_t)(q * 4 + so) * PITA + (uint32_t)c4 * 8;
            split2(pS[q].x, pS[q].y, h0, l0);
            split2(pS[q].z, pS[q].w, h1, l1);
            sts64(uRsH + off, h0, h1);
            sts64(uRsL + off, l0, l1);
            split2(pR[q].x, pR[q].y, h0, l0);
            split2(pR[q].z, pR[q].w, h1, l1);
            sts64(uRrH + off, h0, h1);
            sts64(uRrL + off, l0, l1);
        }
        {
            uint32_t h32, l32;
            split2(pO, 0.f, h32, l32);
            *(u16*)(sOt + od * OPIT + oo * 2)             = (u16)h32;
            *(u16*)(sOt + DS * OPIT + od * OPIT + oo * 2) = (u16)l32;
        }
        __syncthreads();

        if (kc + 1 < NCHA) LOADA((kc + 1) * KCA);

        uint32_t bOh[4], bOl[4];
        {
            uint32_t oaddr = uOH + brow_ * OPIT + bcol_ * 2;
            ldm_x4(bOh, oaddr);
            ldm_x4(bOl, oaddr + DS * OPIT);
        }
#pragma unroll
        for (int mt = 0; mt < 2; mt++) {
            uint32_t aoff = krow * PITA + (uint32_t)(wid * 32 + mt * 16) * 2 + mcol * 2;
            uint32_t ash[4], asl[4], arh[4], arl[4];
            ldm_x4t(ash, uRsH + aoff);
            ldm_x4t(asl, uRsL + aoff);
            ldm_x4t(arh, uRrH + aoff);
            ldm_x4t(arl, uRrL + aoff);
#pragma unroll
            for (int nt = 0; nt < 2; nt++) {
                mma16816(accS[mt][nt], ash, bOh + nt * 2);
                mma16816(accS[mt][nt], ash, bOl + nt * 2);
                mma16816(accS[mt][nt], asl, bOh + nt * 2);
                mma16816(accR[mt][nt], arh, bOh + nt * 2);
                mma16816(accR[mt][nt], arh, bOl + nt * 2);
                mma16816(accR[mt][nt], arl, bOh + nt * 2);
            }
        }
    }
#undef LOADA

    __syncthreads();
    float* sM = (float*)sStage;
#pragma unroll
    for (int mt = 0; mt < 2; mt++) {
        int rl = wid * 32 + mt * 16 + (lid >> 2);
#pragma unroll
        for (int nt = 0; nt < 2; nt++) {
            int c = nt * 8 + (lid & 3) * 2;
            *(float2*)(sM + rl * 34 + c)            = make_float2(accS[mt][nt][0], accS[mt][nt][1]);
            *(float2*)(sM + (rl + 8) * 34 + c)      = make_float2(accS[mt][nt][2], accS[mt][nt][3]);
            *(float2*)(sM + rl * 34 + 16 + c)       = make_float2(accR[mt][nt][0], accR[mt][nt][1]);
            *(float2*)(sM + (rl + 8) * 34 + 16 + c) = make_float2(accR[mt][nt][2], accR[mt][nt][3]);
        }
    }
    __syncthreads();

    const int r = tid;
    u64 mp[16];
    const u64* mrow = (const u64*)(sM + r * 34);
#pragma unroll
    for (int j = 0; j < 16; j++) mp[j] = mrow[j];

    const float* Rab = Ra + (size_t)b * DR * NR + r0 + r;
    u64 rap[4];
#pragma unroll
    for (int j = 0; j < 4; j++)
        rap[j] = pack2(Rab[(size_t)(2 * j) * NR], Rab[(size_t)(2 * j + 1) * NR]);

    u16* EH = g_Ehi + (size_t)b * DE * NR + r0 + r;
    u16* EL = g_Elo + (size_t)b * DE * NR + r0 + r;
#pragma unroll 2
    for (int e = 0; e < DE; e++) {
        const u64* wrow = sW + e * 20;
        u64 a = 0ull;
#pragma unroll
        for (int j = 0; j < 16; j++) a = ffma2(wrow[j], mp[j], a);
#pragma unroll
        for (int j = 0; j < 4; j++)  a = ffma2(wrow[16 + j], rap[j], a);
        float2 v = unpack2(a);
        float val = v.x + v.y + sbr[e];
        uint32_t h32, l32;
        split2(val, 0.f, h32, l32);
        EH[(size_t)e * NR] = (u16)h32;
        EL[(size_t)e * NR] = (u16)l32;
    }
}

// ============================================================================
// Kernel B: E_hat[z][b][o][e] = sum_{r in z} R_r[b,o,r] * E[b,e,r]
// mma.sync bf16, 3 limb products. DOUBLE-BUFFERED smem, ONE sync per chunk:
//   iter k: LDG(k+1) -> compute(k) from buf[k&1] -> STS(k+1) -> sync
// grid (16, BATCH, ZB=4) = 256 CTAs, block 256, 2 CTAs/SM (120KB smem/SM).
// ============================================================================
__global__ void __launch_bounds__(256, 2)
kernelB(const float* __restrict__ Rr)
{
    extern __shared__ __align__(128) char sB[];

    const int tid = threadIdx.x;
    const int wid = tid >> 5;
    const int lid = tid & 31;
    const int wm  = wid & 3;
    const int wn  = wid >> 2;
    const int o0  = blockIdx.x * 128;
    const int b   = blockIdx.y;
    const int z   = blockIdx.z;

    const uint32_t uB0 = smem_u32(sB);

    const float* Ag  = Rr    + (size_t)b * NO * NR + (size_t)z * KZ;
    const u16*   BgH = g_Ehi + (size_t)b * DE * NR + (size_t)z * KZ;
    const u16*   BgL = g_Elo + (size_t)b * DE * NR + (size_t)z * KZ;

    const int arow = tid >> 1, akh = (tid & 1) * 16;
    const int brow = tid >> 2, bkq = (tid & 3) * 8;

    const uint32_t a_lrow = (uint32_t)((wm * 32) + (((lid >> 3) & 1) * 8) + (lid & 7));
    const uint32_t a_lcol = (uint32_t)((lid >> 4) * 8);
    const uint32_t b_lrow = (uint32_t)((wn * 32) + (((lid >> 3) >> 1) * 8) + (lid & 7));
    const uint32_t b_lcol = (uint32_t)(((lid >> 3) & 1) * 8);

    float acc[2][4][4];
#pragma unroll
    for (int i = 0; i < 2; i++)
#pragma unroll
        for (int j = 0; j < 4; j++)
#pragma unroll
            for (int v = 0; v < 4; v++) acc[i][j][v] = 0.f;

    float4 av[4];
    uint4  bvh, bvl;

#define LOADB(cb) do {                                                        \
    const float* ap = Ag + (size_t)(o0 + arow) * NR + (cb) + akh;             \
    _Pragma("unroll")                                                         \
    for (int q = 0; q < 4; q++) av[q] = *(const float4*)(ap + 4 * q);         \
    bvh = *(const uint4*)(BgH + (size_t)brow * NR + (cb) + bkq);              \
    bvl = *(const uint4*)(BgL + (size_t)brow * NR + (cb) + bkq);              \
} while (0)

#define STOREB(base) do {                                                     \
    _Pragma("unroll")                                                         \
    for (int q = 0; q < 4; q++) {                                             \
        uint32_t h0, h1, l0, l1;                                              \
        split2(av[q].x, av[q].y, h0, l0);                                     \
        split2(av[q].z, av[q].w, h1, l1);                                     \
        uint32_t off = (uint32_t)arow * PITCH + (uint32_t)(akh + 4 * q) * 2;  \
        sts64((base) + off, h0, h1);                                          \
        sts64((base) + BOF_AL + off, l0, l1);                                 \
    }                                                                         \
    {                                                                         \
        uint32_t off = (uint32_t)brow * PITCH + (uint32_t)bkq * 2;            \
        sts128((base) + BOF_BH + off, bvh.x, bvh.y, bvh.z, bvh.w);            \
        sts128((base) + BOF_BL + off, bvl.x, bvl.y, bvl.z, bvl.w);            \
    }                                                                         \
} while (0)

    // prologue: chunk 0 -> buf 0
    LOADB(0);
    STOREB(uB0);
    __syncthreads();

    for (int kc = 0; kc < NCH; kc++) {
        const uint32_t cbase = uB0 + (uint32_t)(kc & 1) * BUFSZ;
        const uint32_t nbase = uB0 + (uint32_t)((kc + 1) & 1) * BUFSZ;

        if (kc + 1 < NCH) LOADB((kc + 1) * KC);

        // compute chunk kc from cbase
#pragma unroll
        for (int ks = 0; ks < 2; ks++) {
            const uint32_t koff = (uint32_t)(ks * 16) * 2;
            uint32_t ah[2][4], al[2][4];
            uint32_t bh[4][2], bl[4][2];
#pragma unroll
            for (int mt = 0; mt < 2; mt++) {
                uint32_t addr = (a_lrow + mt * 16) * PITCH + a_lcol * 2 + koff;
                ldm_x4(ah[mt], cbase + addr);
                ldm_x4(al[mt], cbase + BOF_AL + addr);
            }
#pragma unroll
            for (int tp = 0; tp < 2; tp++) {
                uint32_t addr = (b_lrow + tp * 16) * PITCH + b_lcol * 2 + koff;
                uint32_t rh[4], rl[4];
                ldm_x4(rh, cbase + BOF_BH + addr);
                ldm_x4(rl, cbase + BOF_BL + addr);
                bh[2 * tp][0] = rh[0]; bh[2 * tp][1] = rh[1];
                bh[2 * tp + 1][0] = rh[2]; bh[2 * tp + 1][1] = rh[3];
                bl[2 * tp][0] = rl[0]; bl[2 * tp][1] = rl[1];
                bl[2 * tp + 1][0] = rl[2]; bl[2 * tp + 1][1] = rl[3];
            }
#pragma unroll
            for (int mt = 0; mt < 2; mt++)
#pragma unroll
                for (int nt = 0; nt < 4; nt++) {
                    mma16816(acc[mt][nt], ah[mt], bh[nt]);
                    mma16816(acc[mt][nt], ah[mt], bl[nt]);
                    mma16816(acc[mt][nt], al[mt], bh[nt]);
                }
        }

        if (kc + 1 < NCH) STOREB(nbase);
        __syncthreads();
    }
#undef LOADB
#undef STOREB

    float* outb = g_Ehp + ((size_t)(z * BATCH + b) * NO) * DE;
#pragma unroll
    for (int mt = 0; mt < 2; mt++) {
        int o = o0 + wm * 32 + mt * 16 + (lid >> 2);
#pragma unroll
        for (int nt = 0; nt < 4; nt++) {
            int e = wn * 32 + nt * 8 + (lid & 3) * 2;
            float* p = outb + (size_t)o * DE + e;
            *(float2*)p = make_float2(acc[mt][nt][0], acc[mt][nt][1]);
            *(float2*)(p + 8 * DE) = make_float2(acc[mt][nt][2], acc[mt][nt][3]);
        }
    }
}

// ============================================================================
// Kernel C: P = W_o@[O;X;sum_z E_hat_z]+b_o ; scores = W_s@P+b_s ; softmax
// ============================================================================
__global__ void __launch_bounds__(256, 1)
kernelC(const float* __restrict__ O, const float* __restrict__ X,
        const float* __restrict__ Wo, const float* __restrict__ bo,
        const float* __restrict__ Ws, const float* __restrict__ bs,
        float* __restrict__ out)
{
    __shared__ u64 sWo[88 * 32];
    __shared__ u64 sWs[NC * 32];
    __shared__ float sbo[DP];
    __shared__ float sbs[NC];

    const int tid = threadIdx.x;
    const int b   = blockIdx.y;
    const int o   = blockIdx.x * 256 + tid;

    for (int idx = tid; idx < 88 * 32; idx += 256) {
        int f = idx >> 5, p2 = idx & 31;
        sWo[f * 32 + p2] = pack2(Wo[(size_t)(2 * p2) * 88 + f],
                                 Wo[(size_t)(2 * p2 + 1) * 88 + f]);
    }
    for (int idx = tid; idx < NC * 32; idx += 256) {
        int c = idx >> 5, p2 = idx & 31;
        float2 w = *(const float2*)(Ws + (size_t)c * DP + 2 * p2);
        sWs[c * 32 + p2] = pack2(w.x, w.y);
    }
    if (tid < DP) sbo[tid] = bo[tid];
    if (tid < NC) sbs[tid] = bs[tid];
    __syncthreads();

    u64 P[32];
#pragma unroll
    for (int p2 = 0; p2 < 32; p2++) P[p2] = pack2(sbo[2 * p2], sbo[2 * p2 + 1]);

    const float* Ob = O + (size_t)b * DS * NO + o;
    const float* Xb = X + (size_t)b * DX * NO + o;

#pragma unroll 4
    for (int f = 0; f < DS; f++) {
        float cf = Ob[(size_t)f * NO];
        u64 c2 = pack2(cf, cf);
        const u64* wrow = sWo + f * 32;
#pragma unroll
        for (int p2 = 0; p2 < 32; p2++) P[p2] = ffma2(wrow[p2], c2, P[p2]);
    }
#pragma unroll 4
    for (int f = 0; f < DX; f++) {
        float cf = Xb[(size_t)f * NO];
        u64 c2 = pack2(cf, cf);
        const u64* wrow = sWo + (DS + f) * 32;
#pragma unroll
        for (int p2 = 0; p2 < 32; p2++) P[p2] = ffma2(wrow[p2], c2, P[p2]);
    }
    const float* ep0 = g_Ehp + ((size_t)b * NO + o) * DE;
    const size_t SSTR = (size_t)BATCH * NO * DE;
#pragma unroll 4
    for (int f4 = 0; f4 < 16; f4++) {
        float4 v0 = *(const float4*)(ep0 + 4 * f4);
        float4 v1 = *(const float4*)(ep0 + SSTR + 4 * f4);
        float4 v2 = *(const float4*)(ep0 + 2 * SSTR + 4 * f4);
        float4 v3 = *(const float4*)(ep0 + 3 * SSTR + 4 * f4);
        float cf[4] = {(v0.x + v1.x) + (v2.x + v3.x),
                       (v0.y + v1.y) + (v2.y + v3.y),
                       (v0.z + v1.z) + (v2.z + v3.z),
                       (v0.w + v1.w) + (v2.w + v3.w)};
#pragma unroll
        for (int j = 0; j < 4; j++) {
            u64 c2 = pack2(cf[j], cf[j]);
            const u64* wrow = sWo + (DS + DX + 4 * f4 + j) * 32;
#pragma unroll
            for (int p2 = 0; p2 < 32; p2++) P[p2] = ffma2(wrow[p2], c2, P[p2]);
        }
    }

    float sc[NC];
#pragma unroll
    for (int c = 0; c < NC; c++) {
        const u64* wrow = sWs + c * 32;
        u64 acc = 0ull;
#pragma unroll
        for (int p2 = 0; p2 < 32; p2++) acc = ffma2(wrow[p2], P[p2], acc);
        float2 a = unpack2(acc);
        sc[c] = a.x + a.y + sbs[c];
    }

    float mx = sc[0];
#pragma unroll
    for (int c = 1; c < NC; c++) mx = fmaxf(mx, sc[c]);
    float sum = 0.f;
#pragma unroll
    for (int c = 0; c < NC; c++) { sc[c] = expf(sc[c] - mx); sum += sc[c]; }
    float inv = 1.f / sum;
#pragma unroll
    for (int c = 0; c < NC; c++)
        out[((size_t)b * NC + c) * NO + o] = sc[c] * inv;
}

// ============================================================================
extern "C" void kernel_launch(void* const* d_in, const int* in_sizes, int n_in,
                              void* d_out, int out_size)
{
    const float* O  = (const float*)d_in[0];
    const float* Rs = (const float*)d_in[1];
    const float* Rr = (const float*)d_in[2];
    const float* Ra = (const float*)d_in[3];
    const float* X  = (const float*)d_in[4];
    const float* Wr = (const float*)d_in[5];
    const float* br = (const float*)d_in[6];
    const float* Wo = (const float*)d_in[7];
    const float* bo = (const float*)d_in[8];
    const float* Ws = (const float*)d_in[9];
    const float* bs = (const float*)d_in[10];
    float* out = (float*)d_out;
    (void)in_sizes; (void)n_in; (void)out_size;

    int smB = 2 * BUFSZ;   // 61440 B
    cudaFuncSetAttribute(kernelB, cudaFuncAttributeMaxDynamicSharedMemorySize, smB);

    kernelA<<<dim3(NR / RT, BATCH), 256>>>(O, Rs, Rr, Ra, Wr, br);
    kernelB<<<dim3(NO / 128, BATCH, ZB), 256, smB>>>(Rr);
    kernelC<<<dim3(NO / 256, BATCH), 256>>>(O, X, Wo, bo, Ws, bs, out);
}